// round 9
// baseline (speedup 1.0000x reference)
#include <cuda_runtime.h>
#include <cuda_fp16.h>
#include <cstdint>

// Problem constants
#define BB 16
#define TT 4096
#define DD 768
#define NBOX 1024
#define MAXB 128
#define DDETR 256
#define VIS_ELEMS (BB*MAXB*DD)
#define MASK_ELEMS (BB*MAXB)
#define NC 64

// ---------------- scratch (device globals) -----------------------------------
__device__ __align__(16) float g_partial[BB*NC*DD];
__device__ __align__(16) float g_x[BB*DD];
__device__ __align__(16) float g_h1t[BB*DD];
__device__ __align__(16) float g_h1d[BB*DD];
__device__ __align__(16) float g_xt[BB*DD];
__device__ __align__(16) float g_hb[BB*DD];          // folded bias for gemm_h
__device__ int g_pos[NBOX];

// fp16 hi/lo operand arrays (row-major, k contiguous)
__device__ __align__(16) __half g_w1h[768*256],  g_w1l[768*256];
__device__ __align__(16) __half g_w2h[768*768],  g_w2l[768*768];
__device__ __align__(16) __half g_wph[768*768],  g_wpl[768*768];   // pw[:,768:]
__device__ __align__(16) __half g_feath[1024*256], g_featl[1024*256];
__device__ __align__(16) __half g_fm1h[1024*768],  g_fm1l[1024*768];
__device__ __align__(16) __half g_fmh[1024*768],   g_fml[1024*768];

// ---------------- helpers -------------------------------------------------------
__device__ __forceinline__ uint32_t smem_u32(const void* p) {
    uint32_t r;
    asm("{ .reg .u64 t; cvta.to.shared.u64 t, %1; cvt.u32.u64 %0, t; }"
        : "=r"(r) : "l"(p));
    return r;
}
#define CP_ASYNC16(dst, src) \
    asm volatile("cp.async.cg.shared.global [%0], [%1], 16;" \
                 :: "r"(dst), "l"(src) : "memory")
#define CP_COMMIT() asm volatile("cp.async.commit_group;" ::: "memory")
#define CP_WAIT(n)  asm volatile("cp.async.wait_group %0;" :: "n"(n) : "memory")

#define LDSM_X4(r0, r1, r2, r3, addr) \
    asm volatile("ldmatrix.sync.aligned.m8n8.x4.shared.b16 {%0,%1,%2,%3}, [%4];" \
                 : "=r"(r0), "=r"(r1), "=r"(r2), "=r"(r3) : "r"(addr))

#define MMA16816(acc, a0, a1, a2, a3, b0, b1) \
    asm volatile("mma.sync.aligned.m16n8k16.row.col.f32.f16.f16.f32 " \
                 "{%0,%1,%2,%3}, {%4,%5,%6,%7}, {%8,%9}, {%0,%1,%2,%3};" \
                 : "+f"((acc)[0]), "+f"((acc)[1]), "+f"((acc)[2]), "+f"((acc)[3]) \
                 : "r"(a0), "r"(a1), "r"(a2), "r"(a3), "r"(b0), "r"(b1))

__device__ __forceinline__ void h2split(float v, __half2* oh, __half2* ol,
                                        float v1) {
    __half h0 = __float2half_rn(v),  h1 = __float2half_rn(v1);
    __half l0 = __float2half_rn(v - __half2float(h0));
    __half l1 = __float2half_rn(v1 - __half2float(h1));
    *oh = __halves2half2(h0, h1);
    *ol = __halves2half2(l0, l1);
}

// ---------------- zero vis_output + segment metadata (merged) --------------------
__global__ void zero_meta_kernel(float4* __restrict__ out,
                                 const int* __restrict__ bboxes,
                                 float* __restrict__ att_mask_out) {
    const int n4 = VIS_ELEMS / 4;
    for (int i = blockIdx.x * blockDim.x + threadIdx.x; i < n4;
         i += gridDim.x * blockDim.x)
        out[i] = make_float4(0.f, 0.f, 0.f, 0.f);

    if (blockIdx.x == gridDim.x - 1) {
        __shared__ int counts[BB];
        __shared__ int offs[BB];
        int t = threadIdx.x;
        if (t < BB) counts[t] = 0;
        __syncthreads();
        for (int n = t; n < NBOX; n += blockDim.x)
            atomicAdd(&counts[bboxes[n * 5]], 1);
        __syncthreads();
        if (t == 0) {
            int s = 0;
            for (int b = 0; b < BB; b++) { offs[b] = s; s += counts[b]; }
        }
        __syncthreads();
        for (int n = t; n < NBOX; n += blockDim.x)
            g_pos[n] = n - offs[bboxes[n * 5]];
        for (int i = t; i < BB * MAXB; i += blockDim.x) {
            int b = i / MAXB, m = i % MAXB;
            att_mask_out[i] = (m < counts[b]) ? 1.0f : 0.0f;
        }
    }
}

// ---------------- mean pass 1 ----------------------------------------------------
__global__ void mean_partial_kernel(const float* __restrict__ in) {
    int b = blockIdx.x >> 6;
    int c = blockIdx.x & 63;
    const float4* p = reinterpret_cast<const float4*>(
        in + ((size_t)b * TT + (size_t)c * 64) * DD) + threadIdx.x;
    float4 acc = make_float4(0.f, 0.f, 0.f, 0.f);
    #pragma unroll 8
    for (int r = 0; r < 64; r++) {
        float4 v = p[(size_t)r * (DD / 4)];
        acc.x += v.x; acc.y += v.y; acc.z += v.z; acc.w += v.w;
    }
    reinterpret_cast<float4*>(g_partial + ((size_t)b * NC + c) * DD)[threadIdx.x] = acc;
}

// ---------------- mean pass 2 ----------------------------------------------------
__global__ void mean_final_kernel() {
    int i = blockIdx.x * blockDim.x + threadIdx.x;
    int b  = i / (DD / 4);
    int c4 = i % (DD / 4);
    const float4* p = reinterpret_cast<const float4*>(g_partial)
                      + (size_t)b * NC * (DD / 4) + c4;
    float4 acc = make_float4(0.f, 0.f, 0.f, 0.f);
    #pragma unroll 8
    for (int c = 0; c < NC; c++) {
        float4 v = p[(size_t)c * (DD / 4)];
        acc.x += v.x; acc.y += v.y; acc.z += v.z; acc.w += v.w;
    }
    const float s = 1.0f / (float)TT;
    acc.x *= s; acc.y *= s; acc.z *= s; acc.w *= s;
    reinterpret_cast<float4*>(g_x)[(size_t)b * (DD / 4) + c4] = acc;
}

// ---------------- small MLP: 1 col/warp, preloaded weight row, grid 192 -----------
__global__ __launch_bounds__(256) void mlp_kernel(int layer,
        const float* __restrict__ wt, const float* __restrict__ bt,
        const float* __restrict__ wd, const float* __restrict__ bd,
        float* __restrict__ retx_out) {
    __shared__ __align__(16) float xs[BB * DD];   // 48KB
    int branch = blockIdx.x / 96;
    const float* in   = (layer == 0) ? g_x : (branch ? g_h1d : g_h1t);
    const float* w    = branch ? wd : wt;
    const float* bias = branch ? bd : bt;
    float* out        = (layer == 0) ? (branch ? g_h1d : g_h1t)
                                     : (branch ? retx_out : g_xt);

    int warp = threadIdx.x >> 5, lane = threadIdx.x & 31;
    int j = (blockIdx.x % 96) * 8 + warp;         // output column
    const float* wr = w + (size_t)j * DD;

    // preload entire weight row slice: 6 independent float4 per lane
    float4 wv[6];
#pragma unroll
    for (int i = 0; i < 6; i++)
        wv[i] = *reinterpret_cast<const float4*>(&wr[i * 128 + lane * 4]);

    {
        const float4* s = reinterpret_cast<const float4*>(in);
        float4* d = reinterpret_cast<float4*>(xs);
        for (int i = threadIdx.x; i < BB * DD / 4; i += 256) d[i] = s[i];
    }
    __syncthreads();

    float acc[BB];
#pragma unroll
    for (int b = 0; b < BB; b++) acc[b] = 0.f;

#pragma unroll
    for (int i = 0; i < 6; i++) {
        int k = i * 128 + lane * 4;
#pragma unroll
        for (int b = 0; b < BB; b++) {
            float4 xv = *reinterpret_cast<const float4*>(&xs[b * DD + k]);
            acc[b] = fmaf(wv[i].x, xv.x, acc[b]);
            acc[b] = fmaf(wv[i].y, xv.y, acc[b]);
            acc[b] = fmaf(wv[i].z, xv.z, acc[b]);
            acc[b] = fmaf(wv[i].w, xv.w, acc[b]);
        }
    }
#pragma unroll
    for (int b = 0; b < BB; b++) {
#pragma unroll
        for (int off = 16; off > 0; off >>= 1)
            acc[b] += __shfl_xor_sync(0xFFFFFFFFu, acc[b], off);
    }
    if (lane == 0) {
        float bb = bias[j];
#pragma unroll
        for (int b = 0; b < BB; b++) {
            float v = acc[b] + bb;
            if (layer == 0) v = fmaxf(v, 0.f);
            out[b * DD + j] = v;
        }
    }
}

// ---------------- hb = pb + xt @ pw[:, :768]^T : 1 col/warp, grid 96 --------------
__global__ __launch_bounds__(256) void hb_kernel(const float* __restrict__ pw,
                                                 const float* __restrict__ pb) {
    __shared__ __align__(16) float xs[BB * DD];
    int warp = threadIdx.x >> 5, lane = threadIdx.x & 31;
    int j = blockIdx.x * 8 + warp;
    const float* wr = pw + (size_t)j * (2 * DD);

    float4 wv[6];
#pragma unroll
    for (int i = 0; i < 6; i++)
        wv[i] = *reinterpret_cast<const float4*>(&wr[i * 128 + lane * 4]);

    {
        const float4* s = reinterpret_cast<const float4*>(g_xt);
        float4* d = reinterpret_cast<float4*>(xs);
        for (int i = threadIdx.x; i < BB * DD / 4; i += 256) d[i] = s[i];
    }
    __syncthreads();

    float acc[BB];
#pragma unroll
    for (int b = 0; b < BB; b++) acc[b] = 0.f;
#pragma unroll
    for (int i = 0; i < 6; i++) {
        int k = i * 128 + lane * 4;
#pragma unroll
        for (int b = 0; b < BB; b++) {
            float4 xv = *reinterpret_cast<const float4*>(&xs[b * DD + k]);
            acc[b] = fmaf(wv[i].x, xv.x, acc[b]);
            acc[b] = fmaf(wv[i].y, xv.y, acc[b]);
            acc[b] = fmaf(wv[i].z, xv.z, acc[b]);
            acc[b] = fmaf(wv[i].w, xv.w, acc[b]);
        }
    }
#pragma unroll
    for (int b = 0; b < BB; b++) {
#pragma unroll
        for (int off = 16; off > 0; off >>= 1)
            acc[b] += __shfl_xor_sync(0xFFFFFFFFu, acc[b], off);
    }
    if (lane == 0) {
        float bb = pb[j];
#pragma unroll
        for (int b = 0; b < BB; b++)
            g_hb[b * DD + j] = acc[b] + bb;
    }
}

// ---------------- convert operands to fp16 hi/lo -----------------------------------
#define CN1 (768*256)
#define CN2 (768*768)
#define CN3 (768*768)
#define CN4 (1024*256)
__global__ void conv_kernel(const float* __restrict__ m1w, const float* __restrict__ m2w,
                            const float* __restrict__ pw,  const float* __restrict__ feat) {
    const int TOT = CN1 + CN2 + CN3 + CN4;
    for (int i = blockIdx.x * blockDim.x + threadIdx.x; i < TOT;
         i += gridDim.x * blockDim.x) {
        float v; __half *oh, *ol; int o;
        if (i < CN1) { o = i; v = m1w[o]; oh = g_w1h; ol = g_w1l; }
        else if (i < CN1 + CN2) { o = i - CN1; v = m2w[o]; oh = g_w2h; ol = g_w2l; }
        else if (i < CN1 + CN2 + CN3) {
            o = i - CN1 - CN2;
            int col = o / 768, k = o - col * 768;
            v = pw[(size_t)col * (2 * DD) + DD + k];
            oh = g_wph; ol = g_wpl;
        } else {
            o = i - CN1 - CN2 - CN3;
            int n = o >> 8, k = o & 255;
            v = feat[(size_t)n * (DDETR + 1) + 1 + k];
            oh = g_feath; ol = g_featl;
        }
        __half h = __float2half_rn(v);
        oh[o] = h;
        ol[o] = __float2half_rn(v - __half2float(h));
    }
}

// ---------------- fp16 split GEMM: 4-stage cp.async, 1 barrier/chunk ---------------
#define NSTG 4
#define ARRB (64*20*4)          // bytes per operand array (5120)
#define STGB (4*ARRB)           // bytes per stage (20480)
#define GEMM_SMEM (NSTG*STGB)   // 81920
__global__ __launch_bounds__(256) void hgemm(int mode,
        const float* __restrict__ bias,
        const int* __restrict__ bboxes,
        float* __restrict__ out_vis) {
    extern __shared__ __align__(16) uint32_t S[];
    __shared__ int simg[64];

    const int tid = threadIdx.x;
    const int bm = blockIdx.x, bn = blockIdx.y;
    const int wid = tid >> 5, lane = tid & 31, gid = lane >> 2, tig = lane & 3;
    const int wm = wid >> 2, wn = wid & 3;     // warp tile: rows wm*32, cols wn*16
    const int K = (mode == 0) ? 256 : 768;
    const int K2 = K >> 1;
    const int nch = K / 32;

    const __half *Ahp, *Alp, *Bhp, *Blp;
    if (mode == 0)      { Ahp = g_feath; Alp = g_featl; Bhp = g_w1h; Blp = g_w1l; }
    else if (mode == 1) { Ahp = g_fm1h;  Alp = g_fm1l;  Bhp = g_w2h; Blp = g_w2l; }
    else                { Ahp = g_fmh;   Alp = g_fml;   Bhp = g_wph; Blp = g_wpl; }

    const uint32_t* gsrc[4];
    gsrc[0] = (const uint32_t*)Ahp + (size_t)(bm * 64) * K2;
    gsrc[1] = (const uint32_t*)Alp + (size_t)(bm * 64) * K2;
    gsrc[2] = (const uint32_t*)Bhp + (size_t)(bn * 64) * K2;
    gsrc[3] = (const uint32_t*)Blp + (size_t)(bn * 64) * K2;

    if (mode == 2 && tid < 64) simg[tid] = bboxes[(bm * 64 + tid) * 5];

    const uint32_t sbase = smem_u32(S);

    const int q = lane >> 3, lm = lane & 7;
    const uint32_t offA = (uint32_t)(((wm * 32 + lm + (q & 1) * 8) * 20
                                      + ((q >> 1) * 4)) * 4);
    const uint32_t offB = (uint32_t)(((wn * 16 + lm + (q >> 1) * 8) * 20
                                      + ((q & 1) * 4)) * 4);

    float acc[2][2][4];
#pragma unroll
    for (int mt = 0; mt < 2; mt++)
#pragma unroll
        for (int nt = 0; nt < 2; nt++)
#pragma unroll
            for (int x = 0; x < 4; x++) acc[mt][nt][x] = 0.f;

#define LOAD_CHUNK(ch, st) do {                                              \
        int _kc2 = (ch) * 16;                                                \
        _Pragma("unroll")                                                    \
        for (int _i = 0; _i < 4; _i++) {                                     \
            int _id = tid + _i * 256;                                        \
            int _arr = _id >> 8;                                             \
            int _rem = _id & 255;                                            \
            int _row = _rem >> 2, _seg = _rem & 3;                           \
            const uint32_t* _gp = gsrc[_arr] + (size_t)_row * K2 + _kc2 + _seg * 4; \
            uint32_t _dst = sbase + (st) * STGB + _arr * ARRB                \
                            + (_row * 20 + _seg * 4) * 4;                    \
            CP_ASYNC16(_dst, _gp);                                           \
        }                                                                    \
    } while (0)

#pragma unroll
    for (int s = 0; s < NSTG - 1; s++) {
        LOAD_CHUNK(s, s);
        CP_COMMIT();
    }

    for (int c = 0; c < nch; c++) {
        CP_WAIT(NSTG - 2);
        __syncthreads();
        if (c + NSTG - 1 < nch) {
            LOAD_CHUNK(c + NSTG - 1, (c + NSTG - 1) & (NSTG - 1));
        }
        CP_COMMIT();

        const uint32_t stb = sbase + (c & (NSTG - 1)) * STGB;
#pragma unroll
        for (int ks = 0; ks < 2; ks++) {
            uint32_t ah0[4], ah1[4], al0[4], al1[4], bh[4], bl[4];
            LDSM_X4(ah0[0], ah0[1], ah0[2], ah0[3], stb + offA + ks * 32);
            LDSM_X4(ah1[0], ah1[1], ah1[2], ah1[3], stb + offA + 1280 + ks * 32);
            LDSM_X4(al0[0], al0[1], al0[2], al0[3], stb + ARRB + offA + ks * 32);
            LDSM_X4(al1[0], al1[1], al1[2], al1[3], stb + ARRB + offA + 1280 + ks * 32);
            LDSM_X4(bh[0],  bh[1],  bh[2],  bh[3],  stb + 2 * ARRB + offB + ks * 32);
            LDSM_X4(bl[0],  bl[1],  bl[2],  bl[3],  stb + 3 * ARRB + offB + ks * 32);
#pragma unroll
            for (int nt = 0; nt < 2; nt++) {
                uint32_t b0 = bh[nt * 2], b1 = bh[nt * 2 + 1];
                uint32_t c0 = bl[nt * 2], c1 = bl[nt * 2 + 1];
                MMA16816(acc[0][nt], ah0[0], ah0[1], ah0[2], ah0[3], b0, b1);
                MMA16816(acc[1][nt], ah1[0], ah1[1], ah1[2], ah1[3], b0, b1);
                MMA16816(acc[0][nt], al0[0], al0[1], al0[2], al0[3], b0, b1);
                MMA16816(acc[1][nt], al1[0], al1[1], al1[2], al1[3], b0, b1);
                MMA16816(acc[0][nt], ah0[0], ah0[1], ah0[2], ah0[3], c0, c1);
                MMA16816(acc[1][nt], ah1[0], ah1[1], ah1[2], ah1[3], c0, c1);
            }
        }
    }
#undef LOAD_CHUNK

    const int col00 = bn * 64 + wn * 16;
    if (mode == 2) {
#pragma unroll
        for (int mt = 0; mt < 2; mt++) {
            int rl0 = wm * 32 + mt * 16 + gid, rl1 = rl0 + 8;
            int p0 = g_pos[bm * 64 + rl0], p1 = g_pos[bm * 64 + rl1];
            int im0 = simg[rl0], im1 = simg[rl1];
#pragma unroll
            for (int nt = 0; nt < 2; nt++) {
                int col = col00 + nt * 8 + tig * 2;
                if (p0 < MAXB) {
                    float* d = out_vis + ((size_t)im0 * MAXB + p0) * DD + col;
                    d[0] = acc[mt][nt][0] + g_hb[im0 * DD + col];
                    d[1] = acc[mt][nt][1] + g_hb[im0 * DD + col + 1];
                }
                if (p1 < MAXB) {
                    float* d = out_vis + ((size_t)im1 * MAXB + p1) * DD + col;
                    d[0] = acc[mt][nt][2] + g_hb[im1 * DD + col];
                    d[1] = acc[mt][nt][3] + g_hb[im1 * DD + col + 1];
                }
            }
        }
    } else {
        __half* oh = (mode == 0) ? g_fm1h : g_fmh;
        __half* ol = (mode == 0) ? g_fm1l : g_fml;
#pragma unroll
        for (int nt = 0; nt < 2; nt++) {
            int col = col00 + nt * 8 + tig * 2;
            float bv0 = bias[col], bv1 = bias[col + 1];
#pragma unroll
            for (int mt = 0; mt < 2; mt++) {
                int r = bm * 64 + wm * 32 + mt * 16 + gid;
                float v00 = acc[mt][nt][0] + bv0, v01 = acc[mt][nt][1] + bv1;
                float v10 = acc[mt][nt][2] + bv0, v11 = acc[mt][nt][3] + bv1;
                if (mode == 0) {
                    v00 = fmaxf(v00, 0.f); v01 = fmaxf(v01, 0.f);
                    v10 = fmaxf(v10, 0.f); v11 = fmaxf(v11, 0.f);
                }
                __half2 hp, lp;
                h2split(v00, &hp, &lp, v01);
                *(__half2*)&oh[(size_t)r * DD + col] = hp;
                *(__half2*)&ol[(size_t)r * DD + col] = lp;
                h2split(v10, &hp, &lp, v11);
                *(__half2*)&oh[(size_t)(r + 8) * DD + col] = hp;
                *(__half2*)&ol[(size_t)(r + 8) * DD + col] = lp;
            }
        }
    }
}

// ---------------- launch: forked graph (A: GEMM chain, B: mean/MLP/hb chain) -------
extern "C" void kernel_launch(void* const* d_in, const int* in_sizes, int n_in,
                              void* d_out, int out_size) {
    (void)in_sizes; (void)n_in; (void)out_size;
    const float* inputs   = (const float*)d_in[0];
    const int*   bboxes   = (const int*)  d_in[1];
    const float* features = (const float*)d_in[2];
    const float* t1w = (const float*)d_in[3],  *t1b = (const float*)d_in[4];
    const float* t2w = (const float*)d_in[5],  *t2b = (const float*)d_in[6];
    const float* d1w = (const float*)d_in[7],  *d1b = (const float*)d_in[8];
    const float* d2w = (const float*)d_in[9],  *d2b = (const float*)d_in[10];
    const float* m1w = (const float*)d_in[11], *m1b = (const float*)d_in[12];
    const float* m2w = (const float*)d_in[13], *m2b = (const float*)d_in[14];
    const float* pw  = (const float*)d_in[15], *pb  = (const float*)d_in[16];

    float* out      = (float*)d_out;
    float* out_vis  = out;
    float* out_mask = out + VIS_ELEMS;
    float* out_retx = out + VIS_ELEMS + MASK_ELEMS;

    cudaFuncSetAttribute(hgemm, cudaFuncAttributeMaxDynamicSharedMemorySize,
                         GEMM_SMEM);

    static cudaStream_t s2 = nullptr;
    static cudaEvent_t eFork = nullptr, eJoin = nullptr;
    if (s2 == nullptr) {
        cudaStreamCreateWithFlags(&s2, cudaStreamNonBlocking);
        cudaEventCreateWithFlags(&eFork, cudaEventDisableTiming);
        cudaEventCreateWithFlags(&eJoin, cudaEventDisableTiming);
    }

    // fork
    cudaEventRecord(eFork, 0);
    cudaStreamWaitEvent(s2, eFork, 0);

    // ---- branch B (stream s2): mean -> MLPs -> hb -> zero+meta ----
    mean_partial_kernel<<<BB * NC, 192, 0, s2>>>(inputs);
    mean_final_kernel<<<12, 256, 0, s2>>>();
    mlp_kernel<<<192, 256, 0, s2>>>(0, t1w, t1b, d1w, d1b, nullptr);
    mlp_kernel<<<192, 256, 0, s2>>>(1, t2w, t2b, d2w, d2b, out_retx);
    hb_kernel<<<96, 256, 0, s2>>>(pw, pb);
    zero_meta_kernel<<<768, 256, 0, s2>>>((float4*)out_vis, bboxes, out_mask);
    cudaEventRecord(eJoin, s2);

    // ---- branch A (default stream): conv -> gemm0 -> gemm1 ----
    conv_kernel<<<640, 256>>>(m1w, m2w, pw, features);
    hgemm<<<dim3(16, 12), 256, GEMM_SMEM>>>(0, m1b, bboxes, nullptr);
    hgemm<<<dim3(16, 12), 256, GEMM_SMEM>>>(1, m2b, bboxes, nullptr);

    // join, then tail (needs both branches)
    cudaStreamWaitEvent(0, eJoin, 0);
    hgemm<<<dim3(16, 12), 256, GEMM_SMEM>>>(2, nullptr, bboxes, out_vis);
}

// round 10
// speedup vs baseline: 1.0477x; 1.0477x over previous
#include <cuda_runtime.h>
#include <cuda_fp16.h>
#include <cstdint>

// Problem constants
#define BB 16
#define TT 4096
#define DD 768
#define NBOX 1024
#define MAXB 128
#define DDETR 256
#define VIS_ELEMS (BB*MAXB*DD)
#define MASK_ELEMS (BB*MAXB)
#define NC 64

// ---------------- scratch (device globals) -----------------------------------
__device__ __align__(16) float g_partial[BB*NC*DD];
__device__ __align__(16) float g_x[BB*DD];
__device__ __align__(16) float g_h1t[BB*DD];
__device__ __align__(16) float g_h1d[BB*DD];
__device__ __align__(16) float g_xt[BB*DD];
__device__ __align__(16) float g_hb[BB*DD];
__device__ int g_pos[NBOX];
__device__ int g_counts[BB];

// fp16 hi/lo operand arrays (row-major, k contiguous)
__device__ __align__(16) __half g_w1h[768*256],  g_w1l[768*256];
__device__ __align__(16) __half g_w2h[768*768],  g_w2l[768*768];
__device__ __align__(16) __half g_wph[768*768],  g_wpl[768*768];   // pw[:,768:]
__device__ __align__(16) __half g_feath[1024*256], g_featl[1024*256];
__device__ __align__(16) __half g_fm1h[1024*768],  g_fm1l[1024*768];
__device__ __align__(16) __half g_fmh[1024*768],   g_fml[1024*768];

// ---------------- helpers -------------------------------------------------------
__device__ __forceinline__ uint32_t smem_u32(const void* p) {
    uint32_t r;
    asm("{ .reg .u64 t; cvta.to.shared.u64 t, %1; cvt.u32.u64 %0, t; }"
        : "=r"(r) : "l"(p));
    return r;
}
#define CP_ASYNC16(dst, src) \
    asm volatile("cp.async.cg.shared.global [%0], [%1], 16;" \
                 :: "r"(dst), "l"(src) : "memory")
#define CP_COMMIT() asm volatile("cp.async.commit_group;" ::: "memory")
#define CP_WAIT(n)  asm volatile("cp.async.wait_group %0;" :: "n"(n) : "memory")

#define LDSM_X4(r0, r1, r2, r3, addr) \
    asm volatile("ldmatrix.sync.aligned.m8n8.x4.shared.b16 {%0,%1,%2,%3}, [%4];" \
                 : "=r"(r0), "=r"(r1), "=r"(r2), "=r"(r3) : "r"(addr))

#define MMA16816(acc, a0, a1, a2, a3, b0, b1) \
    asm volatile("mma.sync.aligned.m16n8k16.row.col.f32.f16.f16.f32 " \
                 "{%0,%1,%2,%3}, {%4,%5,%6,%7}, {%8,%9}, {%0,%1,%2,%3};" \
                 : "+f"((acc)[0]), "+f"((acc)[1]), "+f"((acc)[2]), "+f"((acc)[3]) \
                 : "r"(a0), "r"(a1), "r"(a2), "r"(a3), "r"(b0), "r"(b1))

__device__ __forceinline__ void h2split(float v, __half2* oh, __half2* ol,
                                        float v1) {
    __half h0 = __float2half_rn(v),  h1 = __float2half_rn(v1);
    __half l0 = __float2half_rn(v - __half2float(h0));
    __half l1 = __float2half_rn(v1 - __half2float(h1));
    *oh = __halves2half2(h0, h1);
    *ol = __halves2half2(l0, l1);
}

// ---------------- segment metadata (early, tiny) ---------------------------------
__global__ void meta_kernel(const int* __restrict__ bboxes,
                            float* __restrict__ att_mask_out) {
    __shared__ int counts[BB];
    __shared__ int offs[BB];
    int t = threadIdx.x;
    if (t < BB) counts[t] = 0;
    __syncthreads();
    int im = bboxes[t * 5];
    atomicAdd(&counts[im], 1);
    __syncthreads();
    if (t == 0) {
        int s = 0;
        for (int b = 0; b < BB; b++) { offs[b] = s; s += counts[b]; }
    }
    __syncthreads();
    g_pos[t] = t - offs[im];
    if (t < BB) g_counts[t] = counts[t];
    for (int i = t; i < BB * MAXB; i += NBOX) {
        int b = i / MAXB, m = i % MAXB;
        att_mask_out[i] = (m < counts[b]) ? 1.0f : 0.0f;
    }
}

// ---------------- zero ONLY complement slots (disjoint from gemm2 writes) --------
__global__ void zero_comp_kernel(float4* __restrict__ out) {
    const int n4 = VIS_ELEMS / 4;           // 393216; 192 float4 per row
    for (int i = blockIdx.x * blockDim.x + threadIdx.x; i < n4;
         i += gridDim.x * blockDim.x) {
        int row = i / 192;                   // 0..2047
        int b = row >> 7, m = row & 127;
        if (m >= g_counts[b])
            out[i] = make_float4(0.f, 0.f, 0.f, 0.f);
    }
}

// ---------------- mean pass 1 ----------------------------------------------------
__global__ void mean_partial_kernel(const float* __restrict__ in) {
    int b = blockIdx.x >> 6;
    int c = blockIdx.x & 63;
    const float4* p = reinterpret_cast<const float4*>(
        in + ((size_t)b * TT + (size_t)c * 64) * DD) + threadIdx.x;
    float4 acc = make_float4(0.f, 0.f, 0.f, 0.f);
    #pragma unroll 8
    for (int r = 0; r < 64; r++) {
        float4 v = p[(size_t)r * (DD / 4)];
        acc.x += v.x; acc.y += v.y; acc.z += v.z; acc.w += v.w;
    }
    reinterpret_cast<float4*>(g_partial + ((size_t)b * NC + c) * DD)[threadIdx.x] = acc;
}

// ---------------- mean pass 2 ----------------------------------------------------
__global__ void mean_final_kernel() {
    int i = blockIdx.x * blockDim.x + threadIdx.x;
    int b  = i / (DD / 4);
    int c4 = i % (DD / 4);
    const float4* p = reinterpret_cast<const float4*>(g_partial)
                      + (size_t)b * NC * (DD / 4) + c4;
    float4 acc = make_float4(0.f, 0.f, 0.f, 0.f);
    #pragma unroll 8
    for (int c = 0; c < NC; c++) {
        float4 v = p[(size_t)c * (DD / 4)];
        acc.x += v.x; acc.y += v.y; acc.z += v.z; acc.w += v.w;
    }
    const float s = 1.0f / (float)TT;
    acc.x *= s; acc.y *= s; acc.z *= s; acc.w *= s;
    reinterpret_cast<float4*>(g_x)[(size_t)b * (DD / 4) + c4] = acc;
}

// ---------------- unified small-GEMV layer: k-split, 2 warps/column --------------
// out[b, j] = (relu?) in[b,:] @ w[j,:wstride->768] + bias[j]
// grid 96 (8 cols/block), block 512 (16 warps; warp = (col, k-half))
__global__ __launch_bounds__(512) void mlp2_kernel(
        const float* __restrict__ in, const float* __restrict__ w,
        const float* __restrict__ bias, float* __restrict__ out,
        int do_relu, int wstride) {
    __shared__ __align__(16) float xs[BB * DD];   // 48KB
    __shared__ float sp[8][2][BB];
    const int tid = threadIdx.x, warp = tid >> 5, lane = tid & 31;
    const int col = warp >> 1, kh = warp & 1;
    const int j = blockIdx.x * 8 + col;
    const float* wr = w + (size_t)j * wstride + kh * 384;

    float4 wv[3];
#pragma unroll
    for (int i = 0; i < 3; i++)
        wv[i] = *reinterpret_cast<const float4*>(&wr[i * 128 + lane * 4]);

    {
        const float4* s = reinterpret_cast<const float4*>(in);
        float4* d = reinterpret_cast<float4*>(xs);
        for (int i = tid; i < BB * DD / 4; i += 512) d[i] = s[i];
    }
    __syncthreads();

    float acc[BB];
#pragma unroll
    for (int b = 0; b < BB; b++) acc[b] = 0.f;
#pragma unroll
    for (int i = 0; i < 3; i++) {
        int k = kh * 384 + i * 128 + lane * 4;
#pragma unroll
        for (int b = 0; b < BB; b++) {
            float4 xv = *reinterpret_cast<const float4*>(&xs[b * DD + k]);
            acc[b] = fmaf(wv[i].x, xv.x, acc[b]);
            acc[b] = fmaf(wv[i].y, xv.y, acc[b]);
            acc[b] = fmaf(wv[i].z, xv.z, acc[b]);
            acc[b] = fmaf(wv[i].w, xv.w, acc[b]);
        }
    }
#pragma unroll
    for (int b = 0; b < BB; b++) {
#pragma unroll
        for (int off = 16; off > 0; off >>= 1)
            acc[b] += __shfl_xor_sync(0xFFFFFFFFu, acc[b], off);
    }
    if (lane == 0) {
#pragma unroll
        for (int b = 0; b < BB; b++) sp[col][kh][b] = acc[b];
    }
    __syncthreads();
    if (tid < 128) {
        int c = tid >> 4, b = tid & 15;
        float v = sp[c][0][b] + sp[c][1][b] + bias[blockIdx.x * 8 + c];
        if (do_relu) v = fmaxf(v, 0.f);
        out[b * DD + blockIdx.x * 8 + c] = v;
    }
}

// ---------------- convert operands to fp16 hi/lo -----------------------------------
#define CN1 (768*256)
#define CN2 (768*768)
#define CN3 (768*768)
#define CN4 (1024*256)
__global__ void conv_kernel(const float* __restrict__ m1w, const float* __restrict__ m2w,
                            const float* __restrict__ pw,  const float* __restrict__ feat) {
    const int TOT = CN1 + CN2 + CN3 + CN4;
    for (int i = blockIdx.x * blockDim.x + threadIdx.x; i < TOT;
         i += gridDim.x * blockDim.x) {
        float v; __half *oh, *ol; int o;
        if (i < CN1) { o = i; v = m1w[o]; oh = g_w1h; ol = g_w1l; }
        else if (i < CN1 + CN2) { o = i - CN1; v = m2w[o]; oh = g_w2h; ol = g_w2l; }
        else if (i < CN1 + CN2 + CN3) {
            o = i - CN1 - CN2;
            int col = o / 768, k = o - col * 768;
            v = pw[(size_t)col * (2 * DD) + DD + k];
            oh = g_wph; ol = g_wpl;
        } else {
            o = i - CN1 - CN2 - CN3;
            int n = o >> 8, k = o & 255;
            v = feat[(size_t)n * (DDETR + 1) + 1 + k];
            oh = g_feath; ol = g_featl;
        }
        __half h = __float2half_rn(v);
        oh[o] = h;
        ol[o] = __float2half_rn(v - __half2float(h));
    }
}

// ---------------- fp16 split GEMM: 4-stage cp.async, 1 barrier/chunk ---------------
#define NSTG 4
#define ARRB (64*20*4)
#define STGB (4*ARRB)
#define GEMM_SMEM (NSTG*STGB)
__global__ __launch_bounds__(256) void hgemm(int mode,
        const float* __restrict__ bias,
        const int* __restrict__ bboxes,
        float* __restrict__ out_vis) {
    extern __shared__ __align__(16) uint32_t S[];
    __shared__ int simg[64];

    const int tid = threadIdx.x;
    const int bm = blockIdx.x, bn = blockIdx.y;
    const int wid = tid >> 5, lane = tid & 31, gid = lane >> 2, tig = lane & 3;
    const int wm = wid >> 2, wn = wid & 3;
    const int K = (mode == 0) ? 256 : 768;
    const int K2 = K >> 1;
    const int nch = K / 32;

    const __half *Ahp, *Alp, *Bhp, *Blp;
    if (mode == 0)      { Ahp = g_feath; Alp = g_featl; Bhp = g_w1h; Blp = g_w1l; }
    else if (mode == 1) { Ahp = g_fm1h;  Alp = g_fm1l;  Bhp = g_w2h; Blp = g_w2l; }
    else                { Ahp = g_fmh;   Alp = g_fml;   Bhp = g_wph; Blp = g_wpl; }

    const uint32_t* gsrc[4];
    gsrc[0] = (const uint32_t*)Ahp + (size_t)(bm * 64) * K2;
    gsrc[1] = (const uint32_t*)Alp + (size_t)(bm * 64) * K2;
    gsrc[2] = (const uint32_t*)Bhp + (size_t)(bn * 64) * K2;
    gsrc[3] = (const uint32_t*)Blp + (size_t)(bn * 64) * K2;

    if (mode == 2 && tid < 64) simg[tid] = bboxes[(bm * 64 + tid) * 5];

    const uint32_t sbase = smem_u32(S);

    const int q = lane >> 3, lm = lane & 7;
    const uint32_t offA = (uint32_t)(((wm * 32 + lm + (q & 1) * 8) * 20
                                      + ((q >> 1) * 4)) * 4);
    const uint32_t offB = (uint32_t)(((wn * 16 + lm + (q >> 1) * 8) * 20
                                      + ((q & 1) * 4)) * 4);

    float acc[2][2][4];
#pragma unroll
    for (int mt = 0; mt < 2; mt++)
#pragma unroll
        for (int nt = 0; nt < 2; nt++)
#pragma unroll
            for (int x = 0; x < 4; x++) acc[mt][nt][x] = 0.f;

#define LOAD_CHUNK(ch, st) do {                                              \
        int _kc2 = (ch) * 16;                                                \
        _Pragma("unroll")                                                    \
        for (int _i = 0; _i < 4; _i++) {                                     \
            int _id = tid + _i * 256;                                        \
            int _arr = _id >> 8;                                             \
            int _rem = _id & 255;                                            \
            int _row = _rem >> 2, _seg = _rem & 3;                           \
            const uint32_t* _gp = gsrc[_arr] + (size_t)_row * K2 + _kc2 + _seg * 4; \
            uint32_t _dst = sbase + (st) * STGB + _arr * ARRB                \
                            + (_row * 20 + _seg * 4) * 4;                    \
            CP_ASYNC16(_dst, _gp);                                           \
        }                                                                    \
    } while (0)

#pragma unroll
    for (int s = 0; s < NSTG - 1; s++) {
        LOAD_CHUNK(s, s);
        CP_COMMIT();
    }

    for (int c = 0; c < nch; c++) {
        CP_WAIT(NSTG - 2);
        __syncthreads();
        if (c + NSTG - 1 < nch) {
            LOAD_CHUNK(c + NSTG - 1, (c + NSTG - 1) & (NSTG - 1));
        }
        CP_COMMIT();

        const uint32_t stb = sbase + (c & (NSTG - 1)) * STGB;
#pragma unroll
        for (int ks = 0; ks < 2; ks++) {
            uint32_t ah0[4], ah1[4], al0[4], al1[4], bh[4], bl[4];
            LDSM_X4(ah0[0], ah0[1], ah0[2], ah0[3], stb + offA + ks * 32);
            LDSM_X4(ah1[0], ah1[1], ah1[2], ah1[3], stb + offA + 1280 + ks * 32);
            LDSM_X4(al0[0], al0[1], al0[2], al0[3], stb + ARRB + offA + ks * 32);
            LDSM_X4(al1[0], al1[1], al1[2], al1[3], stb + ARRB + offA + 1280 + ks * 32);
            LDSM_X4(bh[0],  bh[1],  bh[2],  bh[3],  stb + 2 * ARRB + offB + ks * 32);
            LDSM_X4(bl[0],  bl[1],  bl[2],  bl[3],  stb + 3 * ARRB + offB + ks * 32);
#pragma unroll
            for (int nt = 0; nt < 2; nt++) {
                uint32_t b0 = bh[nt * 2], b1 = bh[nt * 2 + 1];
                uint32_t c0 = bl[nt * 2], c1 = bl[nt * 2 + 1];
                MMA16816(acc[0][nt], ah0[0], ah0[1], ah0[2], ah0[3], b0, b1);
                MMA16816(acc[1][nt], ah1[0], ah1[1], ah1[2], ah1[3], b0, b1);
                MMA16816(acc[0][nt], al0[0], al0[1], al0[2], al0[3], b0, b1);
                MMA16816(acc[1][nt], al1[0], al1[1], al1[2], al1[3], b0, b1);
                MMA16816(acc[0][nt], ah0[0], ah0[1], ah0[2], ah0[3], c0, c1);
                MMA16816(acc[1][nt], ah1[0], ah1[1], ah1[2], ah1[3], c0, c1);
            }
        }
    }
#undef LOAD_CHUNK

    const int col00 = bn * 64 + wn * 16;
    if (mode == 2) {
#pragma unroll
        for (int mt = 0; mt < 2; mt++) {
            int rl0 = wm * 32 + mt * 16 + gid, rl1 = rl0 + 8;
            int p0 = g_pos[bm * 64 + rl0], p1 = g_pos[bm * 64 + rl1];
            int im0 = simg[rl0], im1 = simg[rl1];
#pragma unroll
            for (int nt = 0; nt < 2; nt++) {
                int col = col00 + nt * 8 + tig * 2;
                if (p0 < MAXB) {
                    float* d = out_vis + ((size_t)im0 * MAXB + p0) * DD + col;
                    d[0] = acc[mt][nt][0] + g_hb[im0 * DD + col];
                    d[1] = acc[mt][nt][1] + g_hb[im0 * DD + col + 1];
                }
                if (p1 < MAXB) {
                    float* d = out_vis + ((size_t)im1 * MAXB + p1) * DD + col;
                    d[0] = acc[mt][nt][2] + g_hb[im1 * DD + col];
                    d[1] = acc[mt][nt][3] + g_hb[im1 * DD + col + 1];
                }
            }
        }
    } else {
        __half* oh = (mode == 0) ? g_fm1h : g_fmh;
        __half* ol = (mode == 0) ? g_fm1l : g_fml;
#pragma unroll
        for (int nt = 0; nt < 2; nt++) {
            int col = col00 + nt * 8 + tig * 2;
            float bv0 = bias[col], bv1 = bias[col + 1];
#pragma unroll
            for (int mt = 0; mt < 2; mt++) {
                int r = bm * 64 + wm * 32 + mt * 16 + gid;
                float v00 = acc[mt][nt][0] + bv0, v01 = acc[mt][nt][1] + bv1;
                float v10 = acc[mt][nt][2] + bv0, v11 = acc[mt][nt][3] + bv1;
                if (mode == 0) {
                    v00 = fmaxf(v00, 0.f); v01 = fmaxf(v01, 0.f);
                    v10 = fmaxf(v10, 0.f); v11 = fmaxf(v11, 0.f);
                }
                __half2 hp, lp;
                h2split(v00, &hp, &lp, v01);
                *(__half2*)&oh[(size_t)r * DD + col] = hp;
                *(__half2*)&ol[(size_t)r * DD + col] = lp;
                h2split(v10, &hp, &lp, v11);
                *(__half2*)&oh[(size_t)(r + 8) * DD + col] = hp;
                *(__half2*)&ol[(size_t)(r + 8) * DD + col] = lp;
            }
        }
    }
}

// ---------------- launch: 3-stream forked graph ------------------------------------
extern "C" void kernel_launch(void* const* d_in, const int* in_sizes, int n_in,
                              void* d_out, int out_size) {
    (void)in_sizes; (void)n_in; (void)out_size;
    const float* inputs   = (const float*)d_in[0];
    const int*   bboxes   = (const int*)  d_in[1];
    const float* features = (const float*)d_in[2];
    const float* t1w = (const float*)d_in[3],  *t1b = (const float*)d_in[4];
    const float* t2w = (const float*)d_in[5],  *t2b = (const float*)d_in[6];
    const float* d1w = (const float*)d_in[7],  *d1b = (const float*)d_in[8];
    const float* d2w = (const float*)d_in[9],  *d2b = (const float*)d_in[10];
    const float* m1w = (const float*)d_in[11], *m1b = (const float*)d_in[12];
    const float* m2w = (const float*)d_in[13], *m2b = (const float*)d_in[14];
    const float* pw  = (const float*)d_in[15], *pb  = (const float*)d_in[16];

    float* out      = (float*)d_out;
    float* out_vis  = out;
    float* out_mask = out + VIS_ELEMS;
    float* out_retx = out + VIS_ELEMS + MASK_ELEMS;

    cudaFuncSetAttribute(hgemm, cudaFuncAttributeMaxDynamicSharedMemorySize,
                         GEMM_SMEM);

    static cudaStream_t s2 = nullptr, s3 = nullptr;
    static cudaEvent_t eFork = nullptr, eMean = nullptr, eMeta = nullptr,
                       eB = nullptr, eC = nullptr;
    static float *p_x, *p_h1t, *p_h1d, *p_xt, *p_hb;
    if (s2 == nullptr) {
        cudaStreamCreateWithFlags(&s2, cudaStreamNonBlocking);
        cudaStreamCreateWithFlags(&s3, cudaStreamNonBlocking);
        cudaEventCreateWithFlags(&eFork, cudaEventDisableTiming);
        cudaEventCreateWithFlags(&eMean, cudaEventDisableTiming);
        cudaEventCreateWithFlags(&eMeta, cudaEventDisableTiming);
        cudaEventCreateWithFlags(&eB, cudaEventDisableTiming);
        cudaEventCreateWithFlags(&eC, cudaEventDisableTiming);
        cudaGetSymbolAddress((void**)&p_x,   g_x);
        cudaGetSymbolAddress((void**)&p_h1t, g_h1t);
        cudaGetSymbolAddress((void**)&p_h1d, g_h1d);
        cudaGetSymbolAddress((void**)&p_xt,  g_xt);
        cudaGetSymbolAddress((void**)&p_hb,  g_hb);
    }

    // fork
    cudaEventRecord(eFork, 0);
    cudaStreamWaitEvent(s2, eFork, 0);
    cudaStreamWaitEvent(s3, eFork, 0);

    // ---- stream C head: meta (tiny, only needs bboxes) ----
    meta_kernel<<<1, NBOX, 0, s3>>>(bboxes, out_mask);
    cudaEventRecord(eMeta, s3);

    // ---- stream B (critical): mean -> t-chain -> hb ----
    mean_partial_kernel<<<BB * NC, 192, 0, s2>>>(inputs);
    mean_final_kernel<<<12, 256, 0, s2>>>();
    cudaEventRecord(eMean, s2);
    mlp2_kernel<<<96, 512, 0, s2>>>(p_x,   t1w, t1b, p_h1t, 1, DD);
    mlp2_kernel<<<96, 512, 0, s2>>>(p_h1t, t2w, t2b, p_xt,  0, DD);
    mlp2_kernel<<<96, 512, 0, s2>>>(p_xt,  pw,  pb,  p_hb,  0, 2 * DD);
    cudaEventRecord(eB, s2);

    // ---- stream C tail (off-path): d-chain (ret_x) + complement zero ----
    cudaStreamWaitEvent(s3, eMean, 0);
    mlp2_kernel<<<96, 512, 0, s3>>>(p_x,   d1w, d1b, p_h1d,   1, DD);
    mlp2_kernel<<<96, 512, 0, s3>>>(p_h1d, d2w, d2b, out_retx, 0, DD);
    zero_comp_kernel<<<512, 256, 0, s3>>>((float4*)out_vis);
    cudaEventRecord(eC, s3);

    // ---- stream A (default): conv -> gemm0 -> gemm1 ----
    conv_kernel<<<640, 256>>>(m1w, m2w, pw, features);
    hgemm<<<dim3(16, 12), 256, GEMM_SMEM>>>(0, m1b, bboxes, nullptr);
    hgemm<<<dim3(16, 12), 256, GEMM_SMEM>>>(1, m2b, bboxes, nullptr);

    // join: gemm2 needs g_fm (A), g_hb (B), g_pos (meta)
    cudaStreamWaitEvent(0, eB, 0);
    cudaStreamWaitEvent(0, eMeta, 0);
    hgemm<<<dim3(16, 12), 256, GEMM_SMEM>>>(2, nullptr, bboxes, out_vis);

    // graph leaf must include stream C (retx + complement zero)
    cudaStreamWaitEvent(0, eC, 0);
}

// round 11
// speedup vs baseline: 1.0679x; 1.0192x over previous
#include <cuda_runtime.h>
#include <cuda_fp16.h>
#include <cstdint>

// Problem constants
#define BB 16
#define TT 4096
#define DD 768
#define NBOX 1024
#define MAXB 128
#define DDETR 256
#define VIS_ELEMS (BB*MAXB*DD)
#define MASK_ELEMS (BB*MAXB)
#define NC 64

// ---------------- scratch (device globals) -----------------------------------
__device__ __align__(16) float g_partial[BB*NC*DD];
__device__ __align__(16) float g_x[BB*DD];
__device__ __align__(16) float g_h1t[BB*DD];
__device__ __align__(16) float g_h1d[BB*DD];
__device__ __align__(16) float g_xt[BB*DD];
__device__ __align__(16) float g_hb[BB*DD];
__device__ __align__(16) float g_hacc[NBOX*DD];     // gemm2 raw accumulators
__device__ int g_pos[NBOX];
__device__ int g_counts[BB];

// fp16 hi/lo operand arrays (row-major, k contiguous)
__device__ __align__(16) __half g_w1h[768*256],  g_w1l[768*256];
__device__ __align__(16) __half g_w2h[768*768],  g_w2l[768*768];
__device__ __align__(16) __half g_wph[768*768],  g_wpl[768*768];   // pw[:,768:]
__device__ __align__(16) __half g_feath[1024*256], g_featl[1024*256];
__device__ __align__(16) __half g_fm1h[1024*768],  g_fm1l[1024*768];
__device__ __align__(16) __half g_fmh[1024*768],   g_fml[1024*768];

// ---------------- helpers -------------------------------------------------------
__device__ __forceinline__ uint32_t smem_u32(const void* p) {
    uint32_t r;
    asm("{ .reg .u64 t; cvta.to.shared.u64 t, %1; cvt.u32.u64 %0, t; }"
        : "=r"(r) : "l"(p));
    return r;
}
#define CP_ASYNC16(dst, src) \
    asm volatile("cp.async.cg.shared.global [%0], [%1], 16;" \
                 :: "r"(dst), "l"(src) : "memory")
#define CP_COMMIT() asm volatile("cp.async.commit_group;" ::: "memory")
#define CP_WAIT(n)  asm volatile("cp.async.wait_group %0;" :: "n"(n) : "memory")

#define LDSM_X4(r0, r1, r2, r3, addr) \
    asm volatile("ldmatrix.sync.aligned.m8n8.x4.shared.b16 {%0,%1,%2,%3}, [%4];" \
                 : "=r"(r0), "=r"(r1), "=r"(r2), "=r"(r3) : "r"(addr))

#define MMA16816(acc, a0, a1, a2, a3, b0, b1) \
    asm volatile("mma.sync.aligned.m16n8k16.row.col.f32.f16.f16.f32 " \
                 "{%0,%1,%2,%3}, {%4,%5,%6,%7}, {%8,%9}, {%0,%1,%2,%3};" \
                 : "+f"((acc)[0]), "+f"((acc)[1]), "+f"((acc)[2]), "+f"((acc)[3]) \
                 : "r"(a0), "r"(a1), "r"(a2), "r"(a3), "r"(b0), "r"(b1))

__device__ __forceinline__ void h2split(float v, __half2* oh, __half2* ol,
                                        float v1) {
    __half h0 = __float2half_rn(v),  h1 = __float2half_rn(v1);
    __half l0 = __float2half_rn(v - __half2float(h0));
    __half l1 = __float2half_rn(v1 - __half2float(h1));
    *oh = __halves2half2(h0, h1);
    *ol = __halves2half2(l0, l1);
}

// ---------------- segment metadata (early, tiny) ---------------------------------
__global__ void meta_kernel(const int* __restrict__ bboxes,
                            float* __restrict__ att_mask_out) {
    __shared__ int counts[BB];
    __shared__ int offs[BB];
    int t = threadIdx.x;
    if (t < BB) counts[t] = 0;
    __syncthreads();
    int im = bboxes[t * 5];
    atomicAdd(&counts[im], 1);
    __syncthreads();
    if (t == 0) {
        int s = 0;
        for (int b = 0; b < BB; b++) { offs[b] = s; s += counts[b]; }
    }
    __syncthreads();
    g_pos[t] = t - offs[im];
    if (t < BB) g_counts[t] = counts[t];
    for (int i = t; i < BB * MAXB; i += NBOX) {
        int b = i / MAXB, m = i % MAXB;
        att_mask_out[i] = (m < counts[b]) ? 1.0f : 0.0f;
    }
}

// ---------------- zero ONLY complement slots (disjoint from epi writes) ----------
__global__ void zero_comp_kernel(float4* __restrict__ out) {
    const int n4 = VIS_ELEMS / 4;
    for (int i = blockIdx.x * blockDim.x + threadIdx.x; i < n4;
         i += gridDim.x * blockDim.x) {
        int row = i / 192;
        int b = row >> 7, m = row & 127;
        if (m >= g_counts[b])
            out[i] = make_float4(0.f, 0.f, 0.f, 0.f);
    }
}

// ---------------- epilogue: vis[img,pos] = hacc + hb[img] ------------------------
// grid = NBOX blocks, block = 192 (float4 lanes)
__global__ void epi_kernel(const int* __restrict__ bboxes,
                           float* __restrict__ out_vis) {
    int n = blockIdx.x;
    int p = g_pos[n];
    if (p >= MAXB) return;
    int im = bboxes[n * 5];
    int c4 = threadIdx.x * 4;
    float4 a = *reinterpret_cast<const float4*>(&g_hacc[(size_t)n * DD + c4]);
    float4 b = *reinterpret_cast<const float4*>(&g_hb[im * DD + c4]);
    a.x += b.x; a.y += b.y; a.z += b.z; a.w += b.w;
    *reinterpret_cast<float4*>(&out_vis[((size_t)im * MAXB + p) * DD + c4]) = a;
}

// ---------------- mean pass 1 ----------------------------------------------------
__global__ void mean_partial_kernel(const float* __restrict__ in) {
    int b = blockIdx.x >> 6;
    int c = blockIdx.x & 63;
    const float4* p = reinterpret_cast<const float4*>(
        in + ((size_t)b * TT + (size_t)c * 64) * DD) + threadIdx.x;
    float4 acc = make_float4(0.f, 0.f, 0.f, 0.f);
    #pragma unroll 8
    for (int r = 0; r < 64; r++) {
        float4 v = p[(size_t)r * (DD / 4)];
        acc.x += v.x; acc.y += v.y; acc.z += v.z; acc.w += v.w;
    }
    reinterpret_cast<float4*>(g_partial + ((size_t)b * NC + c) * DD)[threadIdx.x] = acc;
}

// ---------------- mean pass 2 ----------------------------------------------------
__global__ void mean_final_kernel() {
    int i = blockIdx.x * blockDim.x + threadIdx.x;
    int b  = i / (DD / 4);
    int c4 = i % (DD / 4);
    const float4* p = reinterpret_cast<const float4*>(g_partial)
                      + (size_t)b * NC * (DD / 4) + c4;
    float4 acc = make_float4(0.f, 0.f, 0.f, 0.f);
    #pragma unroll 8
    for (int c = 0; c < NC; c++) {
        float4 v = p[(size_t)c * (DD / 4)];
        acc.x += v.x; acc.y += v.y; acc.z += v.z; acc.w += v.w;
    }
    const float s = 1.0f / (float)TT;
    acc.x *= s; acc.y *= s; acc.z *= s; acc.w *= s;
    reinterpret_cast<float4*>(g_x)[(size_t)b * (DD / 4) + c4] = acc;
}

// ---------------- small GEMV: no smem staging, k-split 2, grid 192 ----------------
// block 256 = 8 warps = 4 cols x 2 k-halves. x served from L1/L2.
__global__ __launch_bounds__(256) void mlp2_kernel(
        const float* __restrict__ in, const float* __restrict__ w,
        const float* __restrict__ bias, float* __restrict__ out,
        int do_relu, int wstride) {
    __shared__ float sp[4][2][BB];
    const int tid = threadIdx.x, warp = tid >> 5, lane = tid & 31;
    const int col = warp >> 1, kh = warp & 1;
    const int j = blockIdx.x * 4 + col;
    const float* wr = w + (size_t)j * wstride + kh * 384;

    float4 wv[3];
#pragma unroll
    for (int i = 0; i < 3; i++)
        wv[i] = *reinterpret_cast<const float4*>(&wr[i * 128 + lane * 4]);

    float acc[BB];
#pragma unroll
    for (int b = 0; b < BB; b++) acc[b] = 0.f;
#pragma unroll
    for (int i = 0; i < 3; i++) {
        int k = kh * 384 + i * 128 + lane * 4;
#pragma unroll
        for (int b = 0; b < BB; b++) {
            float4 xv = __ldg(reinterpret_cast<const float4*>(&in[b * DD + k]));
            acc[b] = fmaf(wv[i].x, xv.x, acc[b]);
            acc[b] = fmaf(wv[i].y, xv.y, acc[b]);
            acc[b] = fmaf(wv[i].z, xv.z, acc[b]);
            acc[b] = fmaf(wv[i].w, xv.w, acc[b]);
        }
    }
#pragma unroll
    for (int b = 0; b < BB; b++) {
#pragma unroll
        for (int off = 16; off > 0; off >>= 1)
            acc[b] += __shfl_xor_sync(0xFFFFFFFFu, acc[b], off);
    }
    if (lane == 0) {
#pragma unroll
        for (int b = 0; b < BB; b++) sp[col][kh][b] = acc[b];
    }
    __syncthreads();
    if (tid < 64) {
        int c = tid >> 4, b = tid & 15;
        int jj = blockIdx.x * 4 + c;
        float v = sp[c][0][b] + sp[c][1][b] + bias[jj];
        if (do_relu) v = fmaxf(v, 0.f);
        out[b * DD + jj] = v;
    }
}

// ---------------- convert operands to fp16 hi/lo (split in two) -------------------
#define CN1 (768*256)
#define CN2 (768*768)
#define CN3 (768*768)
#define CN4 (1024*256)
// conv0: w1 + feat (what gemm0 needs)
__global__ void conv0_kernel(const float* __restrict__ m1w,
                             const float* __restrict__ feat) {
    const int TOT = CN1 + CN4;
    for (int i = blockIdx.x * blockDim.x + threadIdx.x; i < TOT;
         i += gridDim.x * blockDim.x) {
        float v; __half *oh, *ol; int o;
        if (i < CN1) { o = i; v = m1w[o]; oh = g_w1h; ol = g_w1l; }
        else {
            o = i - CN1;
            int n = o >> 8, k = o & 255;
            v = feat[(size_t)n * (DDETR + 1) + 1 + k];
            oh = g_feath; ol = g_featl;
        }
        __half h = __float2half_rn(v);
        oh[o] = h;
        ol[o] = __float2half_rn(v - __half2float(h));
    }
}
// conv1: w2 + wp (needed by gemm1 / gemm2)
__global__ void conv1_kernel(const float* __restrict__ m2w,
                             const float* __restrict__ pw) {
    const int TOT = CN2 + CN3;
    for (int i = blockIdx.x * blockDim.x + threadIdx.x; i < TOT;
         i += gridDim.x * blockDim.x) {
        float v; __half *oh, *ol; int o;
        if (i < CN2) { o = i; v = m2w[o]; oh = g_w2h; ol = g_w2l; }
        else {
            o = i - CN2;
            int col = o / 768, k = o - col * 768;
            v = pw[(size_t)col * (2 * DD) + DD + k];
            oh = g_wph; ol = g_wpl;
        }
        __half h = __float2half_rn(v);
        oh[o] = h;
        ol[o] = __float2half_rn(v - __half2float(h));
    }
}

// ---------------- fp16 split GEMM: 4-stage cp.async, 1 barrier/chunk ---------------
// mode 0: fm1 = relu(feat @ m1w^T + m1b)   K=256  -> hi/lo
// mode 1: fm  = fm1 @ m2w^T + m2b          K=768  -> hi/lo
// mode 2: hacc = fm @ pw2^T                K=768  -> raw fp32 (no deps on B!)
#define NSTG 4
#define ARRB (64*20*4)
#define STGB (4*ARRB)
#define GEMM_SMEM (NSTG*STGB)
__global__ __launch_bounds__(256) void hgemm(int mode,
        const float* __restrict__ bias) {
    extern __shared__ __align__(16) uint32_t S[];

    const int tid = threadIdx.x;
    const int bm = blockIdx.x, bn = blockIdx.y;
    const int wid = tid >> 5, lane = tid & 31, gid = lane >> 2, tig = lane & 3;
    const int wm = wid >> 2, wn = wid & 3;
    const int K = (mode == 0) ? 256 : 768;
    const int K2 = K >> 1;
    const int nch = K / 32;

    const __half *Ahp, *Alp, *Bhp, *Blp;
    if (mode == 0)      { Ahp = g_feath; Alp = g_featl; Bhp = g_w1h; Blp = g_w1l; }
    else if (mode == 1) { Ahp = g_fm1h;  Alp = g_fm1l;  Bhp = g_w2h; Blp = g_w2l; }
    else                { Ahp = g_fmh;   Alp = g_fml;   Bhp = g_wph; Blp = g_wpl; }

    const uint32_t* gsrc[4];
    gsrc[0] = (const uint32_t*)Ahp + (size_t)(bm * 64) * K2;
    gsrc[1] = (const uint32_t*)Alp + (size_t)(bm * 64) * K2;
    gsrc[2] = (const uint32_t*)Bhp + (size_t)(bn * 64) * K2;
    gsrc[3] = (const uint32_t*)Blp + (size_t)(bn * 64) * K2;

    const uint32_t sbase = smem_u32(S);

    const int q = lane >> 3, lm = lane & 7;
    const uint32_t offA = (uint32_t)(((wm * 32 + lm + (q & 1) * 8) * 20
                                      + ((q >> 1) * 4)) * 4);
    const uint32_t offB = (uint32_t)(((wn * 16 + lm + (q >> 1) * 8) * 20
                                      + ((q & 1) * 4)) * 4);

    float acc[2][2][4];
#pragma unroll
    for (int mt = 0; mt < 2; mt++)
#pragma unroll
        for (int nt = 0; nt < 2; nt++)
#pragma unroll
            for (int x = 0; x < 4; x++) acc[mt][nt][x] = 0.f;

#define LOAD_CHUNK(ch, st) do {                                              \
        int _kc2 = (ch) * 16;                                                \
        _Pragma("unroll")                                                    \
        for (int _i = 0; _i < 4; _i++) {                                     \
            int _id = tid + _i * 256;                                        \
            int _arr = _id >> 8;                                             \
            int _rem = _id & 255;                                            \
            int _row = _rem >> 2, _seg = _rem & 3;                           \
            const uint32_t* _gp = gsrc[_arr] + (size_t)_row * K2 + _kc2 + _seg * 4; \
            uint32_t _dst = sbase + (st) * STGB + _arr * ARRB                \
                            + (_row * 20 + _seg * 4) * 4;                    \
            CP_ASYNC16(_dst, _gp);                                           \
        }                                                                    \
    } while (0)

#pragma unroll
    for (int s = 0; s < NSTG - 1; s++) {
        LOAD_CHUNK(s, s);
        CP_COMMIT();
    }

    for (int c = 0; c < nch; c++) {
        CP_WAIT(NSTG - 2);
        __syncthreads();
        if (c + NSTG - 1 < nch) {
            LOAD_CHUNK(c + NSTG - 1, (c + NSTG - 1) & (NSTG - 1));
        }
        CP_COMMIT();

        const uint32_t stb = sbase + (c & (NSTG - 1)) * STGB;
#pragma unroll
        for (int ks = 0; ks < 2; ks++) {
            uint32_t ah0[4], ah1[4], al0[4], al1[4], bh[4], bl[4];
            LDSM_X4(ah0[0], ah0[1], ah0[2], ah0[3], stb + offA + ks * 32);
            LDSM_X4(ah1[0], ah1[1], ah1[2], ah1[3], stb + offA + 1280 + ks * 32);
            LDSM_X4(al0[0], al0[1], al0[2], al0[3], stb + ARRB + offA + ks * 32);
            LDSM_X4(al1[0], al1[1], al1[2], al1[3], stb + ARRB + offA + 1280 + ks * 32);
            LDSM_X4(bh[0],  bh[1],  bh[2],  bh[3],  stb + 2 * ARRB + offB + ks * 32);
            LDSM_X4(bl[0],  bl[1],  bl[2],  bl[3],  stb + 3 * ARRB + offB + ks * 32);
#pragma unroll
            for (int nt = 0; nt < 2; nt++) {
                uint32_t b0 = bh[nt * 2], b1 = bh[nt * 2 + 1];
                uint32_t c0 = bl[nt * 2], c1 = bl[nt * 2 + 1];
                MMA16816(acc[0][nt], ah0[0], ah0[1], ah0[2], ah0[3], b0, b1);
                MMA16816(acc[1][nt], ah1[0], ah1[1], ah1[2], ah1[3], b0, b1);
                MMA16816(acc[0][nt], al0[0], al0[1], al0[2], al0[3], b0, b1);
                MMA16816(acc[1][nt], al1[0], al1[1], al1[2], al1[3], b0, b1);
                MMA16816(acc[0][nt], ah0[0], ah0[1], ah0[2], ah0[3], c0, c1);
                MMA16816(acc[1][nt], ah1[0], ah1[1], ah1[2], ah1[3], c0, c1);
            }
        }
    }
#undef LOAD_CHUNK

    const int col00 = bn * 64 + wn * 16;
    if (mode == 2) {
        // store raw accumulators; bias/scatter handled by epi_kernel
#pragma unroll
        for (int nt = 0; nt < 2; nt++) {
            int col = col00 + nt * 8 + tig * 2;
#pragma unroll
            for (int mt = 0; mt < 2; mt++) {
                int r = bm * 64 + wm * 32 + mt * 16 + gid;
                float* d0 = &g_hacc[(size_t)r * DD + col];
                d0[0] = acc[mt][nt][0];
                d0[1] = acc[mt][nt][1];
                float* d1 = &g_hacc[(size_t)(r + 8) * DD + col];
                d1[0] = acc[mt][nt][2];
                d1[1] = acc[mt][nt][3];
            }
        }
    } else {
        __half* oh = (mode == 0) ? g_fm1h : g_fmh;
        __half* ol = (mode == 0) ? g_fm1l : g_fml;
#pragma unroll
        for (int nt = 0; nt < 2; nt++) {
            int col = col00 + nt * 8 + tig * 2;
            float bv0 = bias[col], bv1 = bias[col + 1];
#pragma unroll
            for (int mt = 0; mt < 2; mt++) {
                int r = bm * 64 + wm * 32 + mt * 16 + gid;
                float v00 = acc[mt][nt][0] + bv0, v01 = acc[mt][nt][1] + bv1;
                float v10 = acc[mt][nt][2] + bv0, v11 = acc[mt][nt][3] + bv1;
                if (mode == 0) {
                    v00 = fmaxf(v00, 0.f); v01 = fmaxf(v01, 0.f);
                    v10 = fmaxf(v10, 0.f); v11 = fmaxf(v11, 0.f);
                }
                __half2 hp, lp;
                h2split(v00, &hp, &lp, v01);
                *(__half2*)&oh[(size_t)r * DD + col] = hp;
                *(__half2*)&ol[(size_t)r * DD + col] = lp;
                h2split(v10, &hp, &lp, v11);
                *(__half2*)&oh[(size_t)(r + 8) * DD + col] = hp;
                *(__half2*)&ol[(size_t)(r + 8) * DD + col] = lp;
            }
        }
    }
}

// ---------------- launch: 3-stream graph, gemm2 main off the join ------------------
extern "C" void kernel_launch(void* const* d_in, const int* in_sizes, int n_in,
                              void* d_out, int out_size) {
    (void)in_sizes; (void)n_in; (void)out_size;
    const float* inputs   = (const float*)d_in[0];
    const int*   bboxes   = (const int*)  d_in[1];
    const float* features = (const float*)d_in[2];
    const float* t1w = (const float*)d_in[3],  *t1b = (const float*)d_in[4];
    const float* t2w = (const float*)d_in[5],  *t2b = (const float*)d_in[6];
    const float* d1w = (const float*)d_in[7],  *d1b = (const float*)d_in[8];
    const float* d2w = (const float*)d_in[9],  *d2b = (const float*)d_in[10];
    const float* m1w = (const float*)d_in[11], *m1b = (const float*)d_in[12];
    const float* m2w = (const float*)d_in[13], *m2b = (const float*)d_in[14];
    const float* pw  = (const float*)d_in[15], *pb  = (const float*)d_in[16];

    float* out      = (float*)d_out;
    float* out_vis  = out;
    float* out_mask = out + VIS_ELEMS;
    float* out_retx = out + VIS_ELEMS + MASK_ELEMS;

    cudaFuncSetAttribute(hgemm, cudaFuncAttributeMaxDynamicSharedMemorySize,
                         GEMM_SMEM);

    static cudaStream_t s2 = nullptr, s3 = nullptr;
    static cudaEvent_t eFork = nullptr, eMean = nullptr, eMeta = nullptr,
                       eB = nullptr, eC = nullptr, eConv1 = nullptr;
    static float *p_x, *p_h1t, *p_h1d, *p_xt, *p_hb;
    if (s2 == nullptr) {
        cudaStreamCreateWithFlags(&s2, cudaStreamNonBlocking);
        cudaStreamCreateWithFlags(&s3, cudaStreamNonBlocking);
        cudaEventCreateWithFlags(&eFork, cudaEventDisableTiming);
        cudaEventCreateWithFlags(&eMean, cudaEventDisableTiming);
        cudaEventCreateWithFlags(&eMeta, cudaEventDisableTiming);
        cudaEventCreateWithFlags(&eB, cudaEventDisableTiming);
        cudaEventCreateWithFlags(&eC, cudaEventDisableTiming);
        cudaEventCreateWithFlags(&eConv1, cudaEventDisableTiming);
        cudaGetSymbolAddress((void**)&p_x,   g_x);
        cudaGetSymbolAddress((void**)&p_h1t, g_h1t);
        cudaGetSymbolAddress((void**)&p_h1d, g_h1d);
        cudaGetSymbolAddress((void**)&p_xt,  g_xt);
        cudaGetSymbolAddress((void**)&p_hb,  g_hb);
    }

    // fork
    cudaEventRecord(eFork, 0);
    cudaStreamWaitEvent(s2, eFork, 0);
    cudaStreamWaitEvent(s3, eFork, 0);

    // ---- stream C head: conv1 (w2+wp) + meta ----
    conv1_kernel<<<640, 256, 0, s3>>>(m2w, pw);
    cudaEventRecord(eConv1, s3);
    meta_kernel<<<1, NBOX, 0, s3>>>(bboxes, out_mask);
    cudaEventRecord(eMeta, s3);

    // ---- stream B (parallel): mean -> t-chain -> hb ----
    mean_partial_kernel<<<BB * NC, 192, 0, s2>>>(inputs);
    mean_final_kernel<<<12, 256, 0, s2>>>();
    cudaEventRecord(eMean, s2);
    mlp2_kernel<<<192, 256, 0, s2>>>(p_x,   t1w, t1b, p_h1t, 1, DD);
    mlp2_kernel<<<192, 256, 0, s2>>>(p_h1t, t2w, t2b, p_xt,  0, DD);
    mlp2_kernel<<<192, 256, 0, s2>>>(p_xt,  pw,  pb,  p_hb,  0, 2 * DD);
    cudaEventRecord(eB, s2);

    // ---- stream C tail (off-path): d-chain (ret_x) + complement zero ----
    cudaStreamWaitEvent(s3, eMean, 0);
    mlp2_kernel<<<192, 256, 0, s3>>>(p_x,   d1w, d1b, p_h1d,   1, DD);
    mlp2_kernel<<<192, 256, 0, s3>>>(p_h1d, d2w, d2b, out_retx, 0, DD);
    zero_comp_kernel<<<512, 256, 0, s3>>>((float4*)out_vis);
    cudaEventRecord(eC, s3);

    // ---- stream A (default): conv0 -> gemm0 -> gemm1 -> gemm2 main ----
    conv0_kernel<<<448, 256>>>(m1w, features);
    hgemm<<<dim3(16, 12), 256, GEMM_SMEM>>>(0, m1b);
    cudaStreamWaitEvent(0, eConv1, 0);
    hgemm<<<dim3(16, 12), 256, GEMM_SMEM>>>(1, m2b);
    hgemm<<<dim3(16, 12), 256, GEMM_SMEM>>>(2, nullptr);   // no B dependency!

    // ---- join: epilogue needs g_hacc (A), g_hb (B), g_pos (meta) ----
    cudaStreamWaitEvent(0, eB, 0);
    cudaStreamWaitEvent(0, eMeta, 0);
    epi_kernel<<<NBOX, 192>>>(bboxes, out_vis);

    // graph leaf must include stream C (retx + complement zero)
    cudaStreamWaitEvent(0, eC, 0);
}

// round 12
// speedup vs baseline: 1.0885x; 1.0193x over previous
#include <cuda_runtime.h>
#include <cuda_fp16.h>
#include <cstdint>

// Problem constants
#define BB 16
#define TT 4096
#define DD 768
#define NBOX 1024
#define MAXB 128
#define DDETR 256
#define VIS_ELEMS (BB*MAXB*DD)
#define MASK_ELEMS (BB*MAXB)
#define NC 64

// ---------------- scratch (device globals) -----------------------------------
__device__ __align__(16) float g_partial[BB*NC*DD];
__device__ __align__(16) float g_x[BB*DD];
__device__ __align__(16) float g_h1t[BB*DD];
__device__ __align__(16) float g_h1d[BB*DD];
__device__ __align__(16) float g_xt[BB*DD];
__device__ __align__(16) float g_hb[BB*DD];
__device__ __align__(16) float g_hacc[NBOX*DD];     // gemm2 raw accumulators
__device__ int g_pos[NBOX];
__device__ int g_counts[BB];

// fp16 hi/lo operand arrays (row-major, k contiguous)
__device__ __align__(16) __half g_w1h[768*256],  g_w1l[768*256];
__device__ __align__(16) __half g_w2h[768*768],  g_w2l[768*768];
__device__ __align__(16) __half g_wph[768*768],  g_wpl[768*768];   // pw[:,768:]
__device__ __align__(16) __half g_feath[1024*256], g_featl[1024*256];
__device__ __align__(16) __half g_fm1h[1024*768],  g_fm1l[1024*768];
__device__ __align__(16) __half g_fmh[1024*768],   g_fml[1024*768];

// ---------------- helpers -------------------------------------------------------
__device__ __forceinline__ uint32_t smem_u32(const void* p) {
    uint32_t r;
    asm("{ .reg .u64 t; cvta.to.shared.u64 t, %1; cvt.u32.u64 %0, t; }"
        : "=r"(r) : "l"(p));
    return r;
}
#define CP_ASYNC16(dst, src) \
    asm volatile("cp.async.cg.shared.global [%0], [%1], 16;" \
                 :: "r"(dst), "l"(src) : "memory")
#define CP_COMMIT() asm volatile("cp.async.commit_group;" ::: "memory")
#define CP_WAIT(n)  asm volatile("cp.async.wait_group %0;" :: "n"(n) : "memory")

#define LDSM_X4(r0, r1, r2, r3, addr) \
    asm volatile("ldmatrix.sync.aligned.m8n8.x4.shared.b16 {%0,%1,%2,%3}, [%4];" \
                 : "=r"(r0), "=r"(r1), "=r"(r2), "=r"(r3) : "r"(addr))

#define MMA16816(acc, a0, a1, a2, a3, b0, b1) \
    asm volatile("mma.sync.aligned.m16n8k16.row.col.f32.f16.f16.f32 " \
                 "{%0,%1,%2,%3}, {%4,%5,%6,%7}, {%8,%9}, {%0,%1,%2,%3};" \
                 : "+f"((acc)[0]), "+f"((acc)[1]), "+f"((acc)[2]), "+f"((acc)[3]) \
                 : "r"(a0), "r"(a1), "r"(a2), "r"(a3), "r"(b0), "r"(b1))

__device__ __forceinline__ void h2split(float v, __half2* oh, __half2* ol,
                                        float v1) {
    __half h0 = __float2half_rn(v),  h1 = __float2half_rn(v1);
    __half l0 = __float2half_rn(v - __half2float(h0));
    __half l1 = __float2half_rn(v1 - __half2float(h1));
    *oh = __halves2half2(h0, h1);
    *ol = __halves2half2(l0, l1);
}

// ---------------- segment metadata (early, tiny) ---------------------------------
__global__ void meta_kernel(const int* __restrict__ bboxes,
                            float* __restrict__ att_mask_out) {
    __shared__ int counts[BB];
    __shared__ int offs[BB];
    int t = threadIdx.x;
    if (t < BB) counts[t] = 0;
    __syncthreads();
    int im = bboxes[t * 5];
    atomicAdd(&counts[im], 1);
    __syncthreads();
    if (t == 0) {
        int s = 0;
        for (int b = 0; b < BB; b++) { offs[b] = s; s += counts[b]; }
    }
    __syncthreads();
    g_pos[t] = t - offs[im];
    if (t < BB) g_counts[t] = counts[t];
    for (int i = t; i < BB * MAXB; i += NBOX) {
        int b = i / MAXB, m = i % MAXB;
        att_mask_out[i] = (m < counts[b]) ? 1.0f : 0.0f;
    }
}

// ---------------- zero ONLY complement slots (disjoint from epi writes) ----------
__global__ void zero_comp_kernel(float4* __restrict__ out) {
    const int n4 = VIS_ELEMS / 4;
    for (int i = blockIdx.x * blockDim.x + threadIdx.x; i < n4;
         i += gridDim.x * blockDim.x) {
        int row = i / 192;
        int b = row >> 7, m = row & 127;
        if (m >= g_counts[b])
            out[i] = make_float4(0.f, 0.f, 0.f, 0.f);
    }
}

// ---------------- epilogue: vis[img,pos] = hacc + hb[img] ------------------------
__global__ void epi_kernel(const int* __restrict__ bboxes,
                           float* __restrict__ out_vis) {
    int n = blockIdx.x;
    int p = g_pos[n];
    if (p >= MAXB) return;
    int im = bboxes[n * 5];
    int c4 = threadIdx.x * 4;
    float4 a = *reinterpret_cast<const float4*>(&g_hacc[(size_t)n * DD + c4]);
    float4 b = *reinterpret_cast<const float4*>(&g_hb[im * DD + c4]);
    a.x += b.x; a.y += b.y; a.z += b.z; a.w += b.w;
    *reinterpret_cast<float4*>(&out_vis[((size_t)im * MAXB + p) * DD + c4]) = a;
}

// ---------------- mean pass 1 ----------------------------------------------------
__global__ void mean_partial_kernel(const float* __restrict__ in) {
    int b = blockIdx.x >> 6;
    int c = blockIdx.x & 63;
    const float4* p = reinterpret_cast<const float4*>(
        in + ((size_t)b * TT + (size_t)c * 64) * DD) + threadIdx.x;
    float4 acc = make_float4(0.f, 0.f, 0.f, 0.f);
    #pragma unroll 8
    for (int r = 0; r < 64; r++) {
        float4 v = p[(size_t)r * (DD / 4)];
        acc.x += v.x; acc.y += v.y; acc.z += v.z; acc.w += v.w;
    }
    reinterpret_cast<float4*>(g_partial + ((size_t)b * NC + c) * DD)[threadIdx.x] = acc;
}

// ---------------- mean pass 2: warp per float4 output ----------------------------
// 3072 outputs (16 b x 192 c4), 1 warp each; lane l sums chunks l and l+32.
// grid = 384 blocks x 256 threads (8 warps/block).
__global__ void mean_final_kernel() {
    int W = blockIdx.x * 8 + (threadIdx.x >> 5);   // 0..3071
    int lane = threadIdx.x & 31;
    int b  = W / 192;
    int c4 = W - b * 192;
    const float4* base = reinterpret_cast<const float4*>(g_partial)
                         + (size_t)b * NC * 192 + c4;
    float4 v0 = base[(size_t)lane * 192];
    float4 v1 = base[(size_t)(lane + 32) * 192];
    float sx = v0.x + v1.x, sy = v0.y + v1.y, sz = v0.z + v1.z, sw = v0.w + v1.w;
#pragma unroll
    for (int off = 16; off > 0; off >>= 1) {
        sx += __shfl_xor_sync(0xFFFFFFFFu, sx, off);
        sy += __shfl_xor_sync(0xFFFFFFFFu, sy, off);
        sz += __shfl_xor_sync(0xFFFFFFFFu, sz, off);
        sw += __shfl_xor_sync(0xFFFFFFFFu, sw, off);
    }
    if (lane == 0) {
        const float s = 1.0f / (float)TT;
        reinterpret_cast<float4*>(g_x)[(size_t)b * 192 + c4] =
            make_float4(sx * s, sy * s, sz * s, sw * s);
    }
}

// ---------------- small GEMV: no smem staging, k-split 2, grid 192 ----------------
__global__ __launch_bounds__(256) void mlp2_kernel(
        const float* __restrict__ in, const float* __restrict__ w,
        const float* __restrict__ bias, float* __restrict__ out,
        int do_relu, int wstride) {
    __shared__ float sp[4][2][BB];
    const int tid = threadIdx.x, warp = tid >> 5, lane = tid & 31;
    const int col = warp >> 1, kh = warp & 1;
    const int j = blockIdx.x * 4 + col;
    const float* wr = w + (size_t)j * wstride + kh * 384;

    float4 wv[3];
#pragma unroll
    for (int i = 0; i < 3; i++)
        wv[i] = *reinterpret_cast<const float4*>(&wr[i * 128 + lane * 4]);

    float acc[BB];
#pragma unroll
    for (int b = 0; b < BB; b++) acc[b] = 0.f;
#pragma unroll
    for (int i = 0; i < 3; i++) {
        int k = kh * 384 + i * 128 + lane * 4;
#pragma unroll
        for (int b = 0; b < BB; b++) {
            float4 xv = __ldg(reinterpret_cast<const float4*>(&in[b * DD + k]));
            acc[b] = fmaf(wv[i].x, xv.x, acc[b]);
            acc[b] = fmaf(wv[i].y, xv.y, acc[b]);
            acc[b] = fmaf(wv[i].z, xv.z, acc[b]);
            acc[b] = fmaf(wv[i].w, xv.w, acc[b]);
        }
    }
#pragma unroll
    for (int b = 0; b < BB; b++) {
#pragma unroll
        for (int off = 16; off > 0; off >>= 1)
            acc[b] += __shfl_xor_sync(0xFFFFFFFFu, acc[b], off);
    }
    if (lane == 0) {
#pragma unroll
        for (int b = 0; b < BB; b++) sp[col][kh][b] = acc[b];
    }
    __syncthreads();
    if (tid < 64) {
        int c = tid >> 4, b = tid & 15;
        int jj = blockIdx.x * 4 + c;
        float v = sp[c][0][b] + sp[c][1][b] + bias[jj];
        if (do_relu) v = fmaxf(v, 0.f);
        out[b * DD + jj] = v;
    }
}

// ---------------- convert operands to fp16 hi/lo (split in two) -------------------
#define CN1 (768*256)
#define CN2 (768*768)
#define CN3 (768*768)
#define CN4 (1024*256)
__global__ void conv0_kernel(const float* __restrict__ m1w,
                             const float* __restrict__ feat) {
    const int TOT = CN1 + CN4;
    for (int i = blockIdx.x * blockDim.x + threadIdx.x; i < TOT;
         i += gridDim.x * blockDim.x) {
        float v; __half *oh, *ol; int o;
        if (i < CN1) { o = i; v = m1w[o]; oh = g_w1h; ol = g_w1l; }
        else {
            o = i - CN1;
            int n = o >> 8, k = o & 255;
            v = feat[(size_t)n * (DDETR + 1) + 1 + k];
            oh = g_feath; ol = g_featl;
        }
        __half h = __float2half_rn(v);
        oh[o] = h;
        ol[o] = __float2half_rn(v - __half2float(h));
    }
}
__global__ void conv1_kernel(const float* __restrict__ m2w,
                             const float* __restrict__ pw) {
    const int TOT = CN2 + CN3;
    for (int i = blockIdx.x * blockDim.x + threadIdx.x; i < TOT;
         i += gridDim.x * blockDim.x) {
        float v; __half *oh, *ol; int o;
        if (i < CN2) { o = i; v = m2w[o]; oh = g_w2h; ol = g_w2l; }
        else {
            o = i - CN2;
            int col = o / 768, k = o - col * 768;
            v = pw[(size_t)col * (2 * DD) + DD + k];
            oh = g_wph; ol = g_wpl;
        }
        __half h = __float2half_rn(v);
        oh[o] = h;
        ol[o] = __float2half_rn(v - __half2float(h));
    }
}

// ---------------- fp16 split GEMM: 4-stage cp.async, 1 barrier/chunk ---------------
#define NSTG 4
#define ARRB (64*20*4)
#define STGB (4*ARRB)
#define GEMM_SMEM (NSTG*STGB)
__global__ __launch_bounds__(256) void hgemm(int mode,
        const float* __restrict__ bias) {
    extern __shared__ __align__(16) uint32_t S[];

    const int tid = threadIdx.x;
    const int bm = blockIdx.x, bn = blockIdx.y;
    const int wid = tid >> 5, lane = tid & 31, gid = lane >> 2, tig = lane & 3;
    const int wm = wid >> 2, wn = wid & 3;
    const int K = (mode == 0) ? 256 : 768;
    const int K2 = K >> 1;
    const int nch = K / 32;

    const __half *Ahp, *Alp, *Bhp, *Blp;
    if (mode == 0)      { Ahp = g_feath; Alp = g_featl; Bhp = g_w1h; Blp = g_w1l; }
    else if (mode == 1) { Ahp = g_fm1h;  Alp = g_fm1l;  Bhp = g_w2h; Blp = g_w2l; }
    else                { Ahp = g_fmh;   Alp = g_fml;   Bhp = g_wph; Blp = g_wpl; }

    const uint32_t* gsrc[4];
    gsrc[0] = (const uint32_t*)Ahp + (size_t)(bm * 64) * K2;
    gsrc[1] = (const uint32_t*)Alp + (size_t)(bm * 64) * K2;
    gsrc[2] = (const uint32_t*)Bhp + (size_t)(bn * 64) * K2;
    gsrc[3] = (const uint32_t*)Blp + (size_t)(bn * 64) * K2;

    const uint32_t sbase = smem_u32(S);

    const int q = lane >> 3, lm = lane & 7;
    const uint32_t offA = (uint32_t)(((wm * 32 + lm + (q & 1) * 8) * 20
                                      + ((q >> 1) * 4)) * 4);
    const uint32_t offB = (uint32_t)(((wn * 16 + lm + (q >> 1) * 8) * 20
                                      + ((q & 1) * 4)) * 4);

    float acc[2][2][4];
#pragma unroll
    for (int mt = 0; mt < 2; mt++)
#pragma unroll
        for (int nt = 0; nt < 2; nt++)
#pragma unroll
            for (int x = 0; x < 4; x++) acc[mt][nt][x] = 0.f;

#define LOAD_CHUNK(ch, st) do {                                              \
        int _kc2 = (ch) * 16;                                                \
        _Pragma("unroll")                                                    \
        for (int _i = 0; _i < 4; _i++) {                                     \
            int _id = tid + _i * 256;                                        \
            int _arr = _id >> 8;                                             \
            int _rem = _id & 255;                                            \
            int _row = _rem >> 2, _seg = _rem & 3;                           \
            const uint32_t* _gp = gsrc[_arr] + (size_t)_row * K2 + _kc2 + _seg * 4; \
            uint32_t _dst = sbase + (st) * STGB + _arr * ARRB                \
                            + (_row * 20 + _seg * 4) * 4;                    \
            CP_ASYNC16(_dst, _gp);                                           \
        }                                                                    \
    } while (0)

#pragma unroll
    for (int s = 0; s < NSTG - 1; s++) {
        LOAD_CHUNK(s, s);
        CP_COMMIT();
    }

    for (int c = 0; c < nch; c++) {
        CP_WAIT(NSTG - 2);
        __syncthreads();
        if (c + NSTG - 1 < nch) {
            LOAD_CHUNK(c + NSTG - 1, (c + NSTG - 1) & (NSTG - 1));
        }
        CP_COMMIT();

        const uint32_t stb = sbase + (c & (NSTG - 1)) * STGB;
#pragma unroll
        for (int ks = 0; ks < 2; ks++) {
            uint32_t ah0[4], ah1[4], al0[4], al1[4], bh[4], bl[4];
            LDSM_X4(ah0[0], ah0[1], ah0[2], ah0[3], stb + offA + ks * 32);
            LDSM_X4(ah1[0], ah1[1], ah1[2], ah1[3], stb + offA + 1280 + ks * 32);
            LDSM_X4(al0[0], al0[1], al0[2], al0[3], stb + ARRB + offA + ks * 32);
            LDSM_X4(al1[0], al1[1], al1[2], al1[3], stb + ARRB + offA + 1280 + ks * 32);
            LDSM_X4(bh[0],  bh[1],  bh[2],  bh[3],  stb + 2 * ARRB + offB + ks * 32);
            LDSM_X4(bl[0],  bl[1],  bl[2],  bl[3],  stb + 3 * ARRB + offB + ks * 32);
#pragma unroll
            for (int nt = 0; nt < 2; nt++) {
                uint32_t b0 = bh[nt * 2], b1 = bh[nt * 2 + 1];
                uint32_t c0 = bl[nt * 2], c1 = bl[nt * 2 + 1];
                MMA16816(acc[0][nt], ah0[0], ah0[1], ah0[2], ah0[3], b0, b1);
                MMA16816(acc[1][nt], ah1[0], ah1[1], ah1[2], ah1[3], b0, b1);
                MMA16816(acc[0][nt], al0[0], al0[1], al0[2], al0[3], b0, b1);
                MMA16816(acc[1][nt], al1[0], al1[1], al1[2], al1[3], b0, b1);
                MMA16816(acc[0][nt], ah0[0], ah0[1], ah0[2], ah0[3], c0, c1);
                MMA16816(acc[1][nt], ah1[0], ah1[1], ah1[2], ah1[3], c0, c1);
            }
        }
    }
#undef LOAD_CHUNK

    const int col00 = bn * 64 + wn * 16;
    if (mode == 2) {
#pragma unroll
        for (int nt = 0; nt < 2; nt++) {
            int col = col00 + nt * 8 + tig * 2;
#pragma unroll
            for (int mt = 0; mt < 2; mt++) {
                int r = bm * 64 + wm * 32 + mt * 16 + gid;
                float* d0 = &g_hacc[(size_t)r * DD + col];
                d0[0] = acc[mt][nt][0];
                d0[1] = acc[mt][nt][1];
                float* d1 = &g_hacc[(size_t)(r + 8) * DD + col];
                d1[0] = acc[mt][nt][2];
                d1[1] = acc[mt][nt][3];
            }
        }
    } else {
        __half* oh = (mode == 0) ? g_fm1h : g_fmh;
        __half* ol = (mode == 0) ? g_fm1l : g_fml;
#pragma unroll
        for (int nt = 0; nt < 2; nt++) {
            int col = col00 + nt * 8 + tig * 2;
            float bv0 = bias[col], bv1 = bias[col + 1];
#pragma unroll
            for (int mt = 0; mt < 2; mt++) {
                int r = bm * 64 + wm * 32 + mt * 16 + gid;
                float v00 = acc[mt][nt][0] + bv0, v01 = acc[mt][nt][1] + bv1;
                float v10 = acc[mt][nt][2] + bv0, v11 = acc[mt][nt][3] + bv1;
                if (mode == 0) {
                    v00 = fmaxf(v00, 0.f); v01 = fmaxf(v01, 0.f);
                    v10 = fmaxf(v10, 0.f); v11 = fmaxf(v11, 0.f);
                }
                __half2 hp, lp;
                h2split(v00, &hp, &lp, v01);
                *(__half2*)&oh[(size_t)r * DD + col] = hp;
                *(__half2*)&ol[(size_t)r * DD + col] = lp;
                h2split(v10, &hp, &lp, v11);
                *(__half2*)&oh[(size_t)(r + 8) * DD + col] = hp;
                *(__half2*)&ol[(size_t)(r + 8) * DD + col] = lp;
            }
        }
    }
}

// ---------------- launch: 3-stream graph, gemm2 main off the join ------------------
extern "C" void kernel_launch(void* const* d_in, const int* in_sizes, int n_in,
                              void* d_out, int out_size) {
    (void)in_sizes; (void)n_in; (void)out_size;
    const float* inputs   = (const float*)d_in[0];
    const int*   bboxes   = (const int*)  d_in[1];
    const float* features = (const float*)d_in[2];
    const float* t1w = (const float*)d_in[3],  *t1b = (const float*)d_in[4];
    const float* t2w = (const float*)d_in[5],  *t2b = (const float*)d_in[6];
    const float* d1w = (const float*)d_in[7],  *d1b = (const float*)d_in[8];
    const float* d2w = (const float*)d_in[9],  *d2b = (const float*)d_in[10];
    const float* m1w = (const float*)d_in[11], *m1b = (const float*)d_in[12];
    const float* m2w = (const float*)d_in[13], *m2b = (const float*)d_in[14];
    const float* pw  = (const float*)d_in[15], *pb  = (const float*)d_in[16];

    float* out      = (float*)d_out;
    float* out_vis  = out;
    float* out_mask = out + VIS_ELEMS;
    float* out_retx = out + VIS_ELEMS + MASK_ELEMS;

    cudaFuncSetAttribute(hgemm, cudaFuncAttributeMaxDynamicSharedMemorySize,
                         GEMM_SMEM);

    static cudaStream_t s2 = nullptr, s3 = nullptr;
    static cudaEvent_t eFork = nullptr, eMean = nullptr, eMeta = nullptr,
                       eB = nullptr, eC = nullptr, eConv1 = nullptr;
    static float *p_x, *p_h1t, *p_h1d, *p_xt, *p_hb;
    if (s2 == nullptr) {
        cudaStreamCreateWithFlags(&s2, cudaStreamNonBlocking);
        cudaStreamCreateWithFlags(&s3, cudaStreamNonBlocking);
        cudaEventCreateWithFlags(&eFork, cudaEventDisableTiming);
        cudaEventCreateWithFlags(&eMean, cudaEventDisableTiming);
        cudaEventCreateWithFlags(&eMeta, cudaEventDisableTiming);
        cudaEventCreateWithFlags(&eB, cudaEventDisableTiming);
        cudaEventCreateWithFlags(&eC, cudaEventDisableTiming);
        cudaEventCreateWithFlags(&eConv1, cudaEventDisableTiming);
        cudaGetSymbolAddress((void**)&p_x,   g_x);
        cudaGetSymbolAddress((void**)&p_h1t, g_h1t);
        cudaGetSymbolAddress((void**)&p_h1d, g_h1d);
        cudaGetSymbolAddress((void**)&p_xt,  g_xt);
        cudaGetSymbolAddress((void**)&p_hb,  g_hb);
    }

    // fork
    cudaEventRecord(eFork, 0);
    cudaStreamWaitEvent(s2, eFork, 0);
    cudaStreamWaitEvent(s3, eFork, 0);

    // ---- stream C head: conv1 (w2+wp) + meta ----
    conv1_kernel<<<640, 256, 0, s3>>>(m2w, pw);
    cudaEventRecord(eConv1, s3);
    meta_kernel<<<1, NBOX, 0, s3>>>(bboxes, out_mask);
    cudaEventRecord(eMeta, s3);

    // ---- stream B (parallel): mean -> t-chain -> hb ----
    mean_partial_kernel<<<BB * NC, 192, 0, s2>>>(inputs);
    mean_final_kernel<<<384, 256, 0, s2>>>();
    cudaEventRecord(eMean, s2);
    mlp2_kernel<<<192, 256, 0, s2>>>(p_x,   t1w, t1b, p_h1t, 1, DD);
    mlp2_kernel<<<192, 256, 0, s2>>>(p_h1t, t2w, t2b, p_xt,  0, DD);
    mlp2_kernel<<<192, 256, 0, s2>>>(p_xt,  pw,  pb,  p_hb,  0, 2 * DD);
    cudaEventRecord(eB, s2);

    // ---- stream C tail (off-path): d-chain (ret_x) + complement zero ----
    cudaStreamWaitEvent(s3, eMean, 0);
    mlp2_kernel<<<192, 256, 0, s3>>>(p_x,   d1w, d1b, p_h1d,   1, DD);
    mlp2_kernel<<<192, 256, 0, s3>>>(p_h1d, d2w, d2b, out_retx, 0, DD);
    zero_comp_kernel<<<512, 256, 0, s3>>>((float4*)out_vis);
    cudaEventRecord(eC, s3);

    // ---- stream A (default): conv0 -> gemm0 -> gemm1 -> gemm2 main ----
    conv0_kernel<<<448, 256>>>(m1w, features);
    hgemm<<<dim3(16, 12), 256, GEMM_SMEM>>>(0, m1b);
    cudaStreamWaitEvent(0, eConv1, 0);
    hgemm<<<dim3(16, 12), 256, GEMM_SMEM>>>(1, m2b);
    hgemm<<<dim3(16, 12), 256, GEMM_SMEM>>>(2, nullptr);

    // ---- join: epilogue needs g_hacc (A), g_hb (B), g_pos (meta) ----
    cudaStreamWaitEvent(0, eB, 0);
    cudaStreamWaitEvent(0, eMeta, 0);
    epi_kernel<<<NBOX, 192>>>(bboxes, out_vis);

    // graph leaf must include stream C (retx + complement zero)
    cudaStreamWaitEvent(0, eC, 0);
}

// round 13
// speedup vs baseline: 1.1322x; 1.0401x over previous
#include <cuda_runtime.h>
#include <cuda_fp16.h>
#include <cstdint>

// Problem constants
#define BB 16
#define TT 4096
#define DD 768
#define NBOX 1024
#define MAXB 128
#define DDETR 256
#define VIS_ELEMS (BB*MAXB*DD)
#define MASK_ELEMS (BB*MAXB)
#define NC 64

// ---------------- scratch (device globals) -----------------------------------
__device__ __align__(16) float g_partial[BB*NC*DD];
__device__ __align__(16) float g_x[BB*DD];
__device__ __align__(16) float g_h1t[BB*DD];
__device__ __align__(16) float g_h1d[BB*DD];
__device__ __align__(16) float g_xt[BB*DD];
__device__ __align__(16) float g_hb[BB*DD];
__device__ __align__(16) float g_hacc[NBOX*DD];     // fused gemm raw accumulators
__device__ __align__(16) float g_cb[DD];            // pw2 @ m2b
__device__ __align__(16) float g_zero[DD];          // zero bias (zero-init)
__device__ int g_pos[NBOX];
__device__ int g_counts[BB];

// fp16 hi/lo operand arrays (row-major, k contiguous)
__device__ __align__(16) __half g_w1h[768*256],  g_w1l[768*256];
__device__ __align__(16) __half g_wph[768*768],  g_wpl[768*768];   // pw[:,768:]
__device__ __align__(16) __half g_w2th[768*768], g_w2tl[768*768];  // m2w^T
__device__ __align__(16) __half g_wch[768*768],  g_wcl[768*768];   // WC = pw2@m2w
__device__ __align__(16) __half g_feath[1024*256], g_featl[1024*256];
__device__ __align__(16) __half g_fm1h[1024*768],  g_fm1l[1024*768];

// ---------------- helpers -------------------------------------------------------
__device__ __forceinline__ uint32_t smem_u32(const void* p) {
    uint32_t r;
    asm("{ .reg .u64 t; cvta.to.shared.u64 t, %1; cvt.u32.u64 %0, t; }"
        : "=r"(r) : "l"(p));
    return r;
}
#define CP_ASYNC16(dst, src) \
    asm volatile("cp.async.cg.shared.global [%0], [%1], 16;" \
                 :: "r"(dst), "l"(src) : "memory")
#define CP_COMMIT() asm volatile("cp.async.commit_group;" ::: "memory")
#define CP_WAIT(n)  asm volatile("cp.async.wait_group %0;" :: "n"(n) : "memory")

#define LDSM_X4(r0, r1, r2, r3, addr) \
    asm volatile("ldmatrix.sync.aligned.m8n8.x4.shared.b16 {%0,%1,%2,%3}, [%4];" \
                 : "=r"(r0), "=r"(r1), "=r"(r2), "=r"(r3) : "r"(addr))

#define MMA16816(acc, a0, a1, a2, a3, b0, b1) \
    asm volatile("mma.sync.aligned.m16n8k16.row.col.f32.f16.f16.f32 " \
                 "{%0,%1,%2,%3}, {%4,%5,%6,%7}, {%8,%9}, {%0,%1,%2,%3};" \
                 : "+f"((acc)[0]), "+f"((acc)[1]), "+f"((acc)[2]), "+f"((acc)[3]) \
                 : "r"(a0), "r"(a1), "r"(a2), "r"(a3), "r"(b0), "r"(b1))

__device__ __forceinline__ void h2split(float v, __half2* oh, __half2* ol,
                                        float v1) {
    __half h0 = __float2half_rn(v),  h1 = __float2half_rn(v1);
    __half l0 = __float2half_rn(v - __half2float(h0));
    __half l1 = __float2half_rn(v1 - __half2float(h1));
    *oh = __halves2half2(h0, h1);
    *ol = __halves2half2(l0, l1);
}

// ---------------- segment metadata (tiny) ----------------------------------------
__global__ void meta_kernel(const int* __restrict__ bboxes,
                            float* __restrict__ att_mask_out) {
    __shared__ int counts[BB];
    __shared__ int offs[BB];
    int t = threadIdx.x;
    if (t < BB) counts[t] = 0;
    __syncthreads();
    int im = bboxes[t * 5];
    atomicAdd(&counts[im], 1);
    __syncthreads();
    if (t == 0) {
        int s = 0;
        for (int b = 0; b < BB; b++) { offs[b] = s; s += counts[b]; }
    }
    __syncthreads();
    g_pos[t] = t - offs[im];
    if (t < BB) g_counts[t] = counts[t];
    for (int i = t; i < BB * MAXB; i += NBOX) {
        int b = i / MAXB, m = i % MAXB;
        att_mask_out[i] = (m < counts[b]) ? 1.0f : 0.0f;
    }
}

// ---------------- zero ONLY complement slots -------------------------------------
__global__ void zero_comp_kernel(float4* __restrict__ out) {
    const int n4 = VIS_ELEMS / 4;
    for (int i = blockIdx.x * blockDim.x + threadIdx.x; i < n4;
         i += gridDim.x * blockDim.x) {
        int row = i / 192;
        int b = row >> 7, m = row & 127;
        if (m >= g_counts[b])
            out[i] = make_float4(0.f, 0.f, 0.f, 0.f);
    }
}

// ---------------- epilogue: vis[img,pos] = hacc + hb[img] + cb -------------------
__global__ void epi_kernel(const int* __restrict__ bboxes,
                           float* __restrict__ out_vis) {
    int n = blockIdx.x;
    int p = g_pos[n];
    if (p >= MAXB) return;
    int im = bboxes[n * 5];
    int c4 = threadIdx.x * 4;
    float4 a = *reinterpret_cast<const float4*>(&g_hacc[(size_t)n * DD + c4]);
    float4 b = *reinterpret_cast<const float4*>(&g_hb[im * DD + c4]);
    float4 c = *reinterpret_cast<const float4*>(&g_cb[c4]);
    a.x += b.x + c.x; a.y += b.y + c.y; a.z += b.z + c.z; a.w += b.w + c.w;
    *reinterpret_cast<float4*>(&out_vis[((size_t)im * MAXB + p) * DD + c4]) = a;
}

// ---------------- mean pass 1 ----------------------------------------------------
__global__ void mean_partial_kernel(const float* __restrict__ in) {
    int b = blockIdx.x >> 6;
    int c = blockIdx.x & 63;
    const float4* p = reinterpret_cast<const float4*>(
        in + ((size_t)b * TT + (size_t)c * 64) * DD) + threadIdx.x;
    float4 acc = make_float4(0.f, 0.f, 0.f, 0.f);
    #pragma unroll 8
    for (int r = 0; r < 64; r++) {
        float4 v = p[(size_t)r * (DD / 4)];
        acc.x += v.x; acc.y += v.y; acc.z += v.z; acc.w += v.w;
    }
    reinterpret_cast<float4*>(g_partial + ((size_t)b * NC + c) * DD)[threadIdx.x] = acc;
}

// ---------------- mean pass 2: warp per float4 output ----------------------------
__global__ void mean_final_kernel() {
    int W = blockIdx.x * 8 + (threadIdx.x >> 5);
    int lane = threadIdx.x & 31;
    int b  = W / 192;
    int c4 = W - b * 192;
    const float4* base = reinterpret_cast<const float4*>(g_partial)
                         + (size_t)b * NC * 192 + c4;
    float4 v0 = base[(size_t)lane * 192];
    float4 v1 = base[(size_t)(lane + 32) * 192];
    float sx = v0.x + v1.x, sy = v0.y + v1.y, sz = v0.z + v1.z, sw = v0.w + v1.w;
#pragma unroll
    for (int off = 16; off > 0; off >>= 1) {
        sx += __shfl_xor_sync(0xFFFFFFFFu, sx, off);
        sy += __shfl_xor_sync(0xFFFFFFFFu, sy, off);
        sz += __shfl_xor_sync(0xFFFFFFFFu, sz, off);
        sw += __shfl_xor_sync(0xFFFFFFFFu, sw, off);
    }
    if (lane == 0) {
        const float s = 1.0f / (float)TT;
        reinterpret_cast<float4*>(g_x)[(size_t)b * 192 + c4] =
            make_float4(sx * s, sy * s, sz * s, sw * s);
    }
}

// ---------------- small GEMV: no smem staging, k-split 2, grid 192 ----------------
__global__ __launch_bounds__(256) void mlp2_kernel(
        const float* __restrict__ in, const float* __restrict__ w,
        const float* __restrict__ bias, float* __restrict__ out,
        int do_relu, int wstride) {
    __shared__ float sp[4][2][BB];
    const int tid = threadIdx.x, warp = tid >> 5, lane = tid & 31;
    const int col = warp >> 1, kh = warp & 1;
    const int j = blockIdx.x * 4 + col;
    const float* wr = w + (size_t)j * wstride + kh * 384;

    float4 wv[3];
#pragma unroll
    for (int i = 0; i < 3; i++)
        wv[i] = *reinterpret_cast<const float4*>(&wr[i * 128 + lane * 4]);

    float acc[BB];
#pragma unroll
    for (int b = 0; b < BB; b++) acc[b] = 0.f;
#pragma unroll
    for (int i = 0; i < 3; i++) {
        int k = kh * 384 + i * 128 + lane * 4;
#pragma unroll
        for (int b = 0; b < BB; b++) {
            float4 xv = __ldg(reinterpret_cast<const float4*>(&in[b * DD + k]));
            acc[b] = fmaf(wv[i].x, xv.x, acc[b]);
            acc[b] = fmaf(wv[i].y, xv.y, acc[b]);
            acc[b] = fmaf(wv[i].z, xv.z, acc[b]);
            acc[b] = fmaf(wv[i].w, xv.w, acc[b]);
        }
    }
#pragma unroll
    for (int b = 0; b < BB; b++) {
#pragma unroll
        for (int off = 16; off > 0; off >>= 1)
            acc[b] += __shfl_xor_sync(0xFFFFFFFFu, acc[b], off);
    }
    if (lane == 0) {
#pragma unroll
        for (int b = 0; b < BB; b++) sp[col][kh][b] = acc[b];
    }
    __syncthreads();
    if (tid < 64) {
        int c = tid >> 4, b = tid & 15;
        int jj = blockIdx.x * 4 + c;
        float v = sp[c][0][b] + sp[c][1][b] + bias[jj];
        if (do_relu) v = fmaxf(v, 0.f);
        out[b * DD + jj] = v;
    }
}

// ---------------- cb = pw2 @ m2b (warp per output) --------------------------------
__global__ void cb_kernel(const float* __restrict__ pw,
                          const float* __restrict__ m2b) {
    int warp = threadIdx.x >> 5, lane = threadIdx.x & 31;
    int j = blockIdx.x * 8 + warp;
    const float* wr = pw + (size_t)j * (2 * DD) + DD;
    float acc = 0.f;
#pragma unroll
    for (int i = 0; i < 6; i++) {
        float4 w4 = *reinterpret_cast<const float4*>(&wr[i * 128 + lane * 4]);
        float4 b4 = *reinterpret_cast<const float4*>(&m2b[i * 128 + lane * 4]);
        acc += w4.x * b4.x + w4.y * b4.y + w4.z * b4.z + w4.w * b4.w;
    }
#pragma unroll
    for (int off = 16; off > 0; off >>= 1)
        acc += __shfl_xor_sync(0xFFFFFFFFu, acc, off);
    if (lane == 0) g_cb[j] = acc;
}

// ---------------- convert: w1 + feat split ----------------------------------------
#define CN1 (768*256)
#define CN4 (1024*256)
__global__ void conv0_kernel(const float* __restrict__ m1w,
                             const float* __restrict__ feat) {
    const int TOT = CN1 + CN4;
    for (int i = blockIdx.x * blockDim.x + threadIdx.x; i < TOT;
         i += gridDim.x * blockDim.x) {
        float v; __half *oh, *ol; int o;
        if (i < CN1) { o = i; v = m1w[o]; oh = g_w1h; ol = g_w1l; }
        else {
            o = i - CN1;
            int n = o >> 8, k = o & 255;
            v = feat[(size_t)n * (DDETR + 1) + 1 + k];
            oh = g_feath; ol = g_featl;
        }
        __half h = __float2half_rn(v);
        oh[o] = h;
        ol[o] = __float2half_rn(v - __half2float(h));
    }
}
// ---------------- convert: pw2 split ----------------------------------------------
__global__ void convp_kernel(const float* __restrict__ pw) {
    const int TOT = 768 * 768;
    for (int i = blockIdx.x * blockDim.x + threadIdx.x; i < TOT;
         i += gridDim.x * blockDim.x) {
        int col = i / 768, k = i - col * 768;
        float v = pw[(size_t)col * (2 * DD) + DD + k];
        __half h = __float2half_rn(v);
        g_wph[i] = h;
        g_wpl[i] = __float2half_rn(v - __half2float(h));
    }
}
// ---------------- transpose + split m2w -> g_w2th/g_w2tl --------------------------
// out[k][c] = split(m2w[c][k]); 32x32 smem tiles, 256 threads.
__global__ void w2t_kernel(const float* __restrict__ m2w) {
    __shared__ float tile[32][33];
    int bx = blockIdx.x, by = blockIdx.y;
    int tx = threadIdx.x & 31, tr = threadIdx.x >> 5;
    for (int r = tr; r < 32; r += 8)
        tile[r][tx] = m2w[(size_t)(by * 32 + r) * 768 + bx * 32 + tx];
    __syncthreads();
    for (int r = tr; r < 32; r += 8) {
        float v = tile[tx][r];
        size_t o = (size_t)(bx * 32 + r) * 768 + by * 32 + tx;
        __half h = __float2half_rn(v);
        g_w2th[o] = h;
        g_w2tl[o] = __float2half_rn(v - __half2float(h));
    }
}

// ---------------- fp16 split GEMM: 4-stage cp.async --------------------------------
// mode 0: fm1 = relu(feat @ m1w^T + m1b)   K=256, grid(16,12) -> hi/lo
// mode 2: hacc = fm1 @ WC^T                K=768, grid(16,12) -> raw fp32
// mode 3: WC   = pw2 @ m2w (via m2wT)      K=768, grid(12,12) -> hi/lo
#define NSTG 4
#define ARRB (64*20*4)
#define STGB (4*ARRB)
#define GEMM_SMEM (NSTG*STGB)
__global__ __launch_bounds__(256) void hgemm(int mode,
        const float* __restrict__ bias) {
    extern __shared__ __align__(16) uint32_t S[];

    const int tid = threadIdx.x;
    const int bm = blockIdx.x, bn = blockIdx.y;
    const int wid = tid >> 5, lane = tid & 31, gid = lane >> 2, tig = lane & 3;
    const int wm = wid >> 2, wn = wid & 3;
    const int K = (mode == 0) ? 256 : 768;
    const int K2 = K >> 1;
    const int nch = K / 32;

    const __half *Ahp, *Alp, *Bhp, *Blp;
    if (mode == 0)      { Ahp = g_feath; Alp = g_featl; Bhp = g_w1h;  Blp = g_w1l;  }
    else if (mode == 2) { Ahp = g_fm1h;  Alp = g_fm1l;  Bhp = g_wch;  Blp = g_wcl;  }
    else                { Ahp = g_wph;   Alp = g_wpl;   Bhp = g_w2th; Blp = g_w2tl; }

    const uint32_t* gsrc[4];
    gsrc[0] = (const uint32_t*)Ahp + (size_t)(bm * 64) * K2;
    gsrc[1] = (const uint32_t*)Alp + (size_t)(bm * 64) * K2;
    gsrc[2] = (const uint32_t*)Bhp + (size_t)(bn * 64) * K2;
    gsrc[3] = (const uint32_t*)Blp + (size_t)(bn * 64) * K2;

    const uint32_t sbase = smem_u32(S);

    const int q = lane >> 3, lm = lane & 7;
    const uint32_t offA = (uint32_t)(((wm * 32 + lm + (q & 1) * 8) * 20
                                      + ((q >> 1) * 4)) * 4);
    const uint32_t offB = (uint32_t)(((wn * 16 + lm + (q >> 1) * 8) * 20
                                      + ((q & 1) * 4)) * 4);

    float acc[2][2][4];
#pragma unroll
    for (int mt = 0; mt < 2; mt++)
#pragma unroll
        for (int nt = 0; nt < 2; nt++)
#pragma unroll
            for (int x = 0; x < 4; x++) acc[mt][nt][x] = 0.f;

#define LOAD_CHUNK(ch, st) do {                                              \
        int _kc2 = (ch) * 16;                                                \
        _Pragma("unroll")                                                    \
        for (int _i = 0; _i < 4; _i++) {                                     \
            int _id = tid + _i * 256;                                        \
            int _arr = _id >> 8;                                             \
            int _rem = _id & 255;                                            \
            int _row = _rem >> 2, _seg = _rem & 3;                           \
            const uint32_t* _gp = gsrc[_arr] + (size_t)_row * K2 + _kc2 + _seg * 4; \
            uint32_t _dst = sbase + (st) * STGB + _arr * ARRB                \
                            + (_row * 20 + _seg * 4) * 4;                    \
            CP_ASYNC16(_dst, _gp);                                           \
        }                                                                    \
    } while (0)

#pragma unroll
    for (int s = 0; s < NSTG - 1; s++) {
        LOAD_CHUNK(s, s);
        CP_COMMIT();
    }

    for (int c = 0; c < nch; c++) {
        CP_WAIT(NSTG - 2);
        __syncthreads();
        if (c + NSTG - 1 < nch) {
            LOAD_CHUNK(c + NSTG - 1, (c + NSTG - 1) & (NSTG - 1));
        }
        CP_COMMIT();

        const uint32_t stb = sbase + (c & (NSTG - 1)) * STGB;
#pragma unroll
        for (int ks = 0; ks < 2; ks++) {
            uint32_t ah0[4], ah1[4], al0[4], al1[4], bh[4], bl[4];
            LDSM_X4(ah0[0], ah0[1], ah0[2], ah0[3], stb + offA + ks * 32);
            LDSM_X4(ah1[0], ah1[1], ah1[2], ah1[3], stb + offA + 1280 + ks * 32);
            LDSM_X4(al0[0], al0[1], al0[2], al0[3], stb + ARRB + offA + ks * 32);
            LDSM_X4(al1[0], al1[1], al1[2], al1[3], stb + ARRB + offA + 1280 + ks * 32);
            LDSM_X4(bh[0],  bh[1],  bh[2],  bh[3],  stb + 2 * ARRB + offB + ks * 32);
            LDSM_X4(bl[0],  bl[1],  bl[2],  bl[3],  stb + 3 * ARRB + offB + ks * 32);
#pragma unroll
            for (int nt = 0; nt < 2; nt++) {
                uint32_t b0 = bh[nt * 2], b1 = bh[nt * 2 + 1];
                uint32_t c0 = bl[nt * 2], c1 = bl[nt * 2 + 1];
                MMA16816(acc[0][nt], ah0[0], ah0[1], ah0[2], ah0[3], b0, b1);
                MMA16816(acc[1][nt], ah1[0], ah1[1], ah1[2], ah1[3], b0, b1);
                MMA16816(acc[0][nt], al0[0], al0[1], al0[2], al0[3], b0, b1);
                MMA16816(acc[1][nt], al1[0], al1[1], al1[2], al1[3], b0, b1);
                MMA16816(acc[0][nt], ah0[0], ah0[1], ah0[2], ah0[3], c0, c1);
                MMA16816(acc[1][nt], ah1[0], ah1[1], ah1[2], ah1[3], c0, c1);
            }
        }
    }
#undef LOAD_CHUNK

    const int col00 = bn * 64 + wn * 16;
    if (mode == 2) {
#pragma unroll
        for (int nt = 0; nt < 2; nt++) {
            int col = col00 + nt * 8 + tig * 2;
#pragma unroll
            for (int mt = 0; mt < 2; mt++) {
                int r = bm * 64 + wm * 32 + mt * 16 + gid;
                float* d0 = &g_hacc[(size_t)r * DD + col];
                d0[0] = acc[mt][nt][0];
                d0[1] = acc[mt][nt][1];
                float* d1 = &g_hacc[(size_t)(r + 8) * DD + col];
                d1[0] = acc[mt][nt][2];
                d1[1] = acc[mt][nt][3];
            }
        }
    } else {
        __half* oh = (mode == 0) ? g_fm1h : g_wch;
        __half* ol = (mode == 0) ? g_fm1l : g_wcl;
#pragma unroll
        for (int nt = 0; nt < 2; nt++) {
            int col = col00 + nt * 8 + tig * 2;
            float bv0 = bias[col], bv1 = bias[col + 1];
#pragma unroll
            for (int mt = 0; mt < 2; mt++) {
                int r = bm * 64 + wm * 32 + mt * 16 + gid;
                float v00 = acc[mt][nt][0] + bv0, v01 = acc[mt][nt][1] + bv1;
                float v10 = acc[mt][nt][2] + bv0, v11 = acc[mt][nt][3] + bv1;
                if (mode == 0) {
                    v00 = fmaxf(v00, 0.f); v01 = fmaxf(v01, 0.f);
                    v10 = fmaxf(v10, 0.f); v11 = fmaxf(v11, 0.f);
                }
                __half2 hp, lp;
                h2split(v00, &hp, &lp, v01);
                *(__half2*)&oh[(size_t)r * DD + col] = hp;
                *(__half2*)&ol[(size_t)r * DD + col] = lp;
                h2split(v10, &hp, &lp, v11);
                *(__half2*)&oh[(size_t)(r + 8) * DD + col] = hp;
                *(__half2*)&ol[(size_t)(r + 8) * DD + col] = lp;
            }
        }
    }
}

// ---------------- launch: 3-stream graph with weight-fold --------------------------
extern "C" void kernel_launch(void* const* d_in, const int* in_sizes, int n_in,
                              void* d_out, int out_size) {
    (void)in_sizes; (void)n_in; (void)out_size;
    const float* inputs   = (const float*)d_in[0];
    const int*   bboxes   = (const int*)  d_in[1];
    const float* features = (const float*)d_in[2];
    const float* t1w = (const float*)d_in[3],  *t1b = (const float*)d_in[4];
    const float* t2w = (const float*)d_in[5],  *t2b = (const float*)d_in[6];
    const float* d1w = (const float*)d_in[7],  *d1b = (const float*)d_in[8];
    const float* d2w = (const float*)d_in[9],  *d2b = (const float*)d_in[10];
    const float* m1w = (const float*)d_in[11], *m1b = (const float*)d_in[12];
    const float* m2w = (const float*)d_in[13], *m2b = (const float*)d_in[14];
    const float* pw  = (const float*)d_in[15], *pb  = (const float*)d_in[16];

    float* out      = (float*)d_out;
    float* out_vis  = out;
    float* out_mask = out + VIS_ELEMS;
    float* out_retx = out + VIS_ELEMS + MASK_ELEMS;

    cudaFuncSetAttribute(hgemm, cudaFuncAttributeMaxDynamicSharedMemorySize,
                         GEMM_SMEM);

    static cudaStream_t s2 = nullptr, s3 = nullptr;
    static cudaEvent_t eFork = nullptr, eMean = nullptr, eMeta = nullptr,
                       eB = nullptr, eC = nullptr, eWC = nullptr;
    static float *p_x, *p_h1t, *p_h1d, *p_xt, *p_hb, *p_zero;
    if (s2 == nullptr) {
        cudaStreamCreateWithFlags(&s2, cudaStreamNonBlocking);
        cudaStreamCreateWithFlags(&s3, cudaStreamNonBlocking);
        cudaEventCreateWithFlags(&eFork, cudaEventDisableTiming);
        cudaEventCreateWithFlags(&eMean, cudaEventDisableTiming);
        cudaEventCreateWithFlags(&eMeta, cudaEventDisableTiming);
        cudaEventCreateWithFlags(&eB, cudaEventDisableTiming);
        cudaEventCreateWithFlags(&eC, cudaEventDisableTiming);
        cudaEventCreateWithFlags(&eWC, cudaEventDisableTiming);
        cudaGetSymbolAddress((void**)&p_x,    g_x);
        cudaGetSymbolAddress((void**)&p_h1t,  g_h1t);
        cudaGetSymbolAddress((void**)&p_h1d,  g_h1d);
        cudaGetSymbolAddress((void**)&p_xt,   g_xt);
        cudaGetSymbolAddress((void**)&p_hb,   g_hb);
        cudaGetSymbolAddress((void**)&p_zero, g_zero);
    }

    // fork
    cudaEventRecord(eFork, 0);
    cudaStreamWaitEvent(s2, eFork, 0);
    cudaStreamWaitEvent(s3, eFork, 0);

    // interleave submission so ncu (-s 5 -c 1) profiles gemmWC (6th launch)
    mean_partial_kernel<<<BB * NC, 192, 0, s2>>>(inputs);         // 1 (B)
    convp_kernel<<<384, 256, 0, s3>>>(pw);                        // 2 (C)
    w2t_kernel<<<dim3(24, 24), 256, 0, s3>>>(m2w);                // 3 (C)
    mean_final_kernel<<<384, 256, 0, s2>>>();                     // 4 (B)
    cudaEventRecord(eMean, s2);
    cb_kernel<<<96, 256, 0, s3>>>(pw, m2b);                       // 5 (C)
    hgemm<<<dim3(12, 12), 256, GEMM_SMEM, s3>>>(3, p_zero);       // 6 (C) WC <- prof
    cudaEventRecord(eWC, s3);

    // ---- stream B: t-chain -> hb ----
    mlp2_kernel<<<192, 256, 0, s2>>>(p_x,   t1w, t1b, p_h1t, 1, DD);
    mlp2_kernel<<<192, 256, 0, s2>>>(p_h1t, t2w, t2b, p_xt,  0, DD);
    mlp2_kernel<<<192, 256, 0, s2>>>(p_xt,  pw,  pb,  p_hb,  0, 2 * DD);
    cudaEventRecord(eB, s2);

    // ---- stream C tail: meta, d-chain (ret_x), complement zero ----
    meta_kernel<<<1, NBOX, 0, s3>>>(bboxes, out_mask);
    cudaEventRecord(eMeta, s3);
    cudaStreamWaitEvent(s3, eMean, 0);
    mlp2_kernel<<<192, 256, 0, s3>>>(p_x,   d1w, d1b, p_h1d,   1, DD);
    mlp2_kernel<<<192, 256, 0, s3>>>(p_h1d, d2w, d2b, out_retx, 0, DD);
    zero_comp_kernel<<<512, 256, 0, s3>>>((float4*)out_vis);
    cudaEventRecord(eC, s3);

    // ---- stream A: conv0 -> gemm0 -> (wait WC) -> fused gemm -> epi ----
    conv0_kernel<<<448, 256>>>(m1w, features);
    hgemm<<<dim3(16, 12), 256, GEMM_SMEM>>>(0, m1b);
    cudaStreamWaitEvent(0, eWC, 0);
    hgemm<<<dim3(16, 12), 256, GEMM_SMEM>>>(2, nullptr);

    cudaStreamWaitEvent(0, eB, 0);
    cudaStreamWaitEvent(0, eMeta, 0);
    epi_kernel<<<NBOX, 192>>>(bboxes, out_vis);

    cudaStreamWaitEvent(0, eC, 0);
}

// round 14
// speedup vs baseline: 1.1713x; 1.0346x over previous
#include <cuda_runtime.h>
#include <cuda_fp16.h>
#include <cstdint>

// Problem constants
#define BB 16
#define TT 4096
#define DD 768
#define NBOX 1024
#define MAXB 128
#define DDETR 256
#define VIS_ELEMS (BB*MAXB*DD)
#define MASK_ELEMS (BB*MAXB)
#define NC 64

// ---------------- scratch (device globals) -----------------------------------
__device__ __align__(16) float g_partial[BB*NC*DD];
__device__ __align__(16) float g_x[BB*DD];
__device__ __align__(16) float g_h1t[BB*DD];
__device__ __align__(16) float g_h1d[BB*DD];
__device__ __align__(16) float g_xt[BB*DD];
__device__ __align__(16) float g_hb[BB*DD];
__device__ __align__(16) float g_hacc[NBOX*DD];      // gemm2 partial (z=0)
__device__ __align__(16) float g_hacc2[NBOX*DD];     // gemm2 partial (z=1)
__device__ __align__(16) float g_wcacc0[768*768];    // gemmWC partial (z=0)
__device__ __align__(16) float g_wcacc1[768*768];    // gemmWC partial (z=1)
__device__ __align__(16) float g_cb[DD];             // pw2 @ m2b
__device__ int g_pos[NBOX];
__device__ int g_counts[BB];

// fp16 hi/lo operand arrays (row-major, k contiguous)
__device__ __align__(16) __half g_w1h[768*256],  g_w1l[768*256];
__device__ __align__(16) __half g_wph[768*768],  g_wpl[768*768];   // pw[:,768:]
__device__ __align__(16) __half g_w2th[768*768], g_w2tl[768*768];  // m2w^T
__device__ __align__(16) __half g_wch[768*768],  g_wcl[768*768];   // WC = pw2@m2w
__device__ __align__(16) __half g_feath[1024*256], g_featl[1024*256];
__device__ __align__(16) __half g_fm1h[1024*768],  g_fm1l[1024*768];

// ---------------- helpers -------------------------------------------------------
__device__ __forceinline__ uint32_t smem_u32(const void* p) {
    uint32_t r;
    asm("{ .reg .u64 t; cvta.to.shared.u64 t, %1; cvt.u32.u64 %0, t; }"
        : "=r"(r) : "l"(p));
    return r;
}
#define CP_ASYNC16(dst, src) \
    asm volatile("cp.async.cg.shared.global [%0], [%1], 16;" \
                 :: "r"(dst), "l"(src) : "memory")
#define CP_COMMIT() asm volatile("cp.async.commit_group;" ::: "memory")
#define CP_WAIT(n)  asm volatile("cp.async.wait_group %0;" :: "n"(n) : "memory")

#define LDSM_X4(r0, r1, r2, r3, addr) \
    asm volatile("ldmatrix.sync.aligned.m8n8.x4.shared.b16 {%0,%1,%2,%3}, [%4];" \
                 : "=r"(r0), "=r"(r1), "=r"(r2), "=r"(r3) : "r"(addr))

#define MMA16816(acc, a0, a1, a2, a3, b0, b1) \
    asm volatile("mma.sync.aligned.m16n8k16.row.col.f32.f16.f16.f32 " \
                 "{%0,%1,%2,%3}, {%4,%5,%6,%7}, {%8,%9}, {%0,%1,%2,%3};" \
                 : "+f"((acc)[0]), "+f"((acc)[1]), "+f"((acc)[2]), "+f"((acc)[3]) \
                 : "r"(a0), "r"(a1), "r"(a2), "r"(a3), "r"(b0), "r"(b1))

__device__ __forceinline__ void h2split(float v, __half2* oh, __half2* ol,
                                        float v1) {
    __half h0 = __float2half_rn(v),  h1 = __float2half_rn(v1);
    __half l0 = __float2half_rn(v - __half2float(h0));
    __half l1 = __float2half_rn(v1 - __half2float(h1));
    *oh = __halves2half2(h0, h1);
    *ol = __halves2half2(l0, l1);
}

// ---------------- segment metadata (tiny) ----------------------------------------
__global__ void meta_kernel(const int* __restrict__ bboxes,
                            float* __restrict__ att_mask_out) {
    __shared__ int counts[BB];
    __shared__ int offs[BB];
    int t = threadIdx.x;
    if (t < BB) counts[t] = 0;
    __syncthreads();
    int im = bboxes[t * 5];
    atomicAdd(&counts[im], 1);
    __syncthreads();
    if (t == 0) {
        int s = 0;
        for (int b = 0; b < BB; b++) { offs[b] = s; s += counts[b]; }
    }
    __syncthreads();
    g_pos[t] = t - offs[im];
    if (t < BB) g_counts[t] = counts[t];
    for (int i = t; i < BB * MAXB; i += NBOX) {
        int b = i / MAXB, m = i % MAXB;
        att_mask_out[i] = (m < counts[b]) ? 1.0f : 0.0f;
    }
}

// ---------------- zero ONLY complement slots -------------------------------------
__global__ void zero_comp_kernel(float4* __restrict__ out) {
    const int n4 = VIS_ELEMS / 4;
    for (int i = blockIdx.x * blockDim.x + threadIdx.x; i < n4;
         i += gridDim.x * blockDim.x) {
        int row = i / 192;
        int b = row >> 7, m = row & 127;
        if (m >= g_counts[b])
            out[i] = make_float4(0.f, 0.f, 0.f, 0.f);
    }
}

// ---------------- epilogue: vis[img,pos] = hacc + hacc2 + hb[img] + cb -----------
__global__ void epi_kernel(const int* __restrict__ bboxes,
                           float* __restrict__ out_vis) {
    int n = blockIdx.x;
    int p = g_pos[n];
    if (p >= MAXB) return;
    int im = bboxes[n * 5];
    int c4 = threadIdx.x * 4;
    float4 a  = *reinterpret_cast<const float4*>(&g_hacc[(size_t)n * DD + c4]);
    float4 a2 = *reinterpret_cast<const float4*>(&g_hacc2[(size_t)n * DD + c4]);
    float4 b  = *reinterpret_cast<const float4*>(&g_hb[im * DD + c4]);
    float4 c  = *reinterpret_cast<const float4*>(&g_cb[c4]);
    a.x += a2.x + b.x + c.x; a.y += a2.y + b.y + c.y;
    a.z += a2.z + b.z + c.z; a.w += a2.w + b.w + c.w;
    *reinterpret_cast<float4*>(&out_vis[((size_t)im * MAXB + p) * DD + c4]) = a;
}

// ---------------- mean pass 1 ----------------------------------------------------
__global__ void mean_partial_kernel(const float* __restrict__ in) {
    int b = blockIdx.x >> 6;
    int c = blockIdx.x & 63;
    const float4* p = reinterpret_cast<const float4*>(
        in + ((size_t)b * TT + (size_t)c * 64) * DD) + threadIdx.x;
    float4 acc = make_float4(0.f, 0.f, 0.f, 0.f);
    #pragma unroll 8
    for (int r = 0; r < 64; r++) {
        float4 v = p[(size_t)r * (DD / 4)];
        acc.x += v.x; acc.y += v.y; acc.z += v.z; acc.w += v.w;
    }
    reinterpret_cast<float4*>(g_partial + ((size_t)b * NC + c) * DD)[threadIdx.x] = acc;
}

// ---------------- mean pass 2: warp per float4 output ----------------------------
__global__ void mean_final_kernel() {
    int W = blockIdx.x * 8 + (threadIdx.x >> 5);
    int lane = threadIdx.x & 31;
    int b  = W / 192;
    int c4 = W - b * 192;
    const float4* base = reinterpret_cast<const float4*>(g_partial)
                         + (size_t)b * NC * 192 + c4;
    float4 v0 = base[(size_t)lane * 192];
    float4 v1 = base[(size_t)(lane + 32) * 192];
    float sx = v0.x + v1.x, sy = v0.y + v1.y, sz = v0.z + v1.z, sw = v0.w + v1.w;
#pragma unroll
    for (int off = 16; off > 0; off >>= 1) {
        sx += __shfl_xor_sync(0xFFFFFFFFu, sx, off);
        sy += __shfl_xor_sync(0xFFFFFFFFu, sy, off);
        sz += __shfl_xor_sync(0xFFFFFFFFu, sz, off);
        sw += __shfl_xor_sync(0xFFFFFFFFu, sw, off);
    }
    if (lane == 0) {
        const float s = 1.0f / (float)TT;
        reinterpret_cast<float4*>(g_x)[(size_t)b * 192 + c4] =
            make_float4(sx * s, sy * s, sz * s, sw * s);
    }
}

// ---------------- small GEMV: no smem staging, k-split 2, grid 192 ----------------
__global__ __launch_bounds__(256) void mlp2_kernel(
        const float* __restrict__ in, const float* __restrict__ w,
        const float* __restrict__ bias, float* __restrict__ out,
        int do_relu, int wstride) {
    __shared__ float sp[4][2][BB];
    const int tid = threadIdx.x, warp = tid >> 5, lane = tid & 31;
    const int col = warp >> 1, kh = warp & 1;
    const int j = blockIdx.x * 4 + col;
    const float* wr = w + (size_t)j * wstride + kh * 384;

    float4 wv[3];
#pragma unroll
    for (int i = 0; i < 3; i++)
        wv[i] = *reinterpret_cast<const float4*>(&wr[i * 128 + lane * 4]);

    float acc[BB];
#pragma unroll
    for (int b = 0; b < BB; b++) acc[b] = 0.f;
#pragma unroll
    for (int i = 0; i < 3; i++) {
        int k = kh * 384 + i * 128 + lane * 4;
#pragma unroll
        for (int b = 0; b < BB; b++) {
            float4 xv = __ldg(reinterpret_cast<const float4*>(&in[b * DD + k]));
            acc[b] = fmaf(wv[i].x, xv.x, acc[b]);
            acc[b] = fmaf(wv[i].y, xv.y, acc[b]);
            acc[b] = fmaf(wv[i].z, xv.z, acc[b]);
            acc[b] = fmaf(wv[i].w, xv.w, acc[b]);
        }
    }
#pragma unroll
    for (int b = 0; b < BB; b++) {
#pragma unroll
        for (int off = 16; off > 0; off >>= 1)
            acc[b] += __shfl_xor_sync(0xFFFFFFFFu, acc[b], off);
    }
    if (lane == 0) {
#pragma unroll
        for (int b = 0; b < BB; b++) sp[col][kh][b] = acc[b];
    }
    __syncthreads();
    if (tid < 64) {
        int c = tid >> 4, b = tid & 15;
        int jj = blockIdx.x * 4 + c;
        float v = sp[c][0][b] + sp[c][1][b] + bias[jj];
        if (do_relu) v = fmaxf(v, 0.f);
        out[b * DD + jj] = v;
    }
}

// ---------------- cb = pw2 @ m2b (warp per output) --------------------------------
__global__ void cb_kernel(const float* __restrict__ pw,
                          const float* __restrict__ m2b) {
    int warp = threadIdx.x >> 5, lane = threadIdx.x & 31;
    int j = blockIdx.x * 8 + warp;
    const float* wr = pw + (size_t)j * (2 * DD) + DD;
    float acc = 0.f;
#pragma unroll
    for (int i = 0; i < 6; i++) {
        float4 w4 = *reinterpret_cast<const float4*>(&wr[i * 128 + lane * 4]);
        float4 b4 = *reinterpret_cast<const float4*>(&m2b[i * 128 + lane * 4]);
        acc += w4.x * b4.x + w4.y * b4.y + w4.z * b4.z + w4.w * b4.w;
    }
#pragma unroll
    for (int off = 16; off > 0; off >>= 1)
        acc += __shfl_xor_sync(0xFFFFFFFFu, acc, off);
    if (lane == 0) g_cb[j] = acc;
}

// ---------------- convert: w1 + feat split ----------------------------------------
#define CN1 (768*256)
#define CN4 (1024*256)
__global__ void conv0_kernel(const float* __restrict__ m1w,
                             const float* __restrict__ feat) {
    const int TOT = CN1 + CN4;
    for (int i = blockIdx.x * blockDim.x + threadIdx.x; i < TOT;
         i += gridDim.x * blockDim.x) {
        float v; __half *oh, *ol; int o;
        if (i < CN1) { o = i; v = m1w[o]; oh = g_w1h; ol = g_w1l; }
        else {
            o = i - CN1;
            int n = o >> 8, k = o & 255;
            v = feat[(size_t)n * (DDETR + 1) + 1 + k];
            oh = g_feath; ol = g_featl;
        }
        __half h = __float2half_rn(v);
        oh[o] = h;
        ol[o] = __float2half_rn(v - __half2float(h));
    }
}
// ---------------- convert: pw2 split ----------------------------------------------
__global__ void convp_kernel(const float* __restrict__ pw) {
    const int TOT = 768 * 768;
    for (int i = blockIdx.x * blockDim.x + threadIdx.x; i < TOT;
         i += gridDim.x * blockDim.x) {
        int col = i / 768, k = i - col * 768;
        float v = pw[(size_t)col * (2 * DD) + DD + k];
        __half h = __float2half_rn(v);
        g_wph[i] = h;
        g_wpl[i] = __float2half_rn(v - __half2float(h));
    }
}
// ---------------- transpose + split m2w -> g_w2th/g_w2tl --------------------------
__global__ void w2t_kernel(const float* __restrict__ m2w) {
    __shared__ float tile[32][33];
    int bx = blockIdx.x, by = blockIdx.y;
    int tx = threadIdx.x & 31, tr = threadIdx.x >> 5;
    for (int r = tr; r < 32; r += 8)
        tile[r][tx] = m2w[(size_t)(by * 32 + r) * 768 + bx * 32 + tx];
    __syncthreads();
    for (int r = tr; r < 32; r += 8) {
        float v = tile[tx][r];
        size_t o = (size_t)(bx * 32 + r) * 768 + by * 32 + tx;
        __half h = __float2half_rn(v);
        g_w2th[o] = h;
        g_w2tl[o] = __float2half_rn(v - __half2float(h));
    }
}

// ---------------- WC reduce: sum partials, split to hi/lo -------------------------
__global__ void wcsplit_kernel() {
    const int TOT = 768 * 768;
    for (int i = blockIdx.x * blockDim.x + threadIdx.x; i < TOT;
         i += gridDim.x * blockDim.x) {
        float v = g_wcacc0[i] + g_wcacc1[i];
        __half h = __float2half_rn(v);
        g_wch[i] = h;
        g_wcl[i] = __float2half_rn(v - __half2float(h));
    }
}

// ---------------- fp16 split GEMM: 3-stage cp.async, split-K via blockIdx.z --------
// mode 0: fm1 = relu(feat @ m1w^T + m1b)   K=256, grid(16,12,1) -> hi/lo
// mode 2: hacc[z] = fm1 @ WC^T (half K)    K=768, grid(16,12,2) -> raw fp32
// mode 3: wcacc[z] = pw2 @ m2wT (half K)   K=768, grid(12,12,2) -> raw fp32
#define NSTG 3
#define ARRB (64*20*4)
#define STGB (4*ARRB)
#define GEMM_SMEM (NSTG*STGB)    // 61440
__global__ __launch_bounds__(256) void hgemm(int mode,
        const float* __restrict__ bias) {
    extern __shared__ __align__(16) uint32_t S[];

    const int tid = threadIdx.x;
    const int bm = blockIdx.x, bn = blockIdx.y, bz = blockIdx.z;
    const int wid = tid >> 5, lane = tid & 31, gid = lane >> 2, tig = lane & 3;
    const int wm = wid >> 2, wn = wid & 3;
    const int K = (mode == 0) ? 256 : 768;
    const int K2 = K >> 1;                       // row stride in uint32
    const int Keff = K / gridDim.z;
    const int nch = Keff / 32;
    const int kb2 = bz * (Keff >> 1);            // k offset in uint32

    const __half *Ahp, *Alp, *Bhp, *Blp;
    if (mode == 0)      { Ahp = g_feath; Alp = g_featl; Bhp = g_w1h;  Blp = g_w1l;  }
    else if (mode == 2) { Ahp = g_fm1h;  Alp = g_fm1l;  Bhp = g_wch;  Blp = g_wcl;  }
    else                { Ahp = g_wph;   Alp = g_wpl;   Bhp = g_w2th; Blp = g_w2tl; }

    const uint32_t* gsrc[4];
    gsrc[0] = (const uint32_t*)Ahp + (size_t)(bm * 64) * K2 + kb2;
    gsrc[1] = (const uint32_t*)Alp + (size_t)(bm * 64) * K2 + kb2;
    gsrc[2] = (const uint32_t*)Bhp + (size_t)(bn * 64) * K2 + kb2;
    gsrc[3] = (const uint32_t*)Blp + (size_t)(bn * 64) * K2 + kb2;

    const uint32_t sbase = smem_u32(S);

    const int q = lane >> 3, lm = lane & 7;
    const uint32_t offA = (uint32_t)(((wm * 32 + lm + (q & 1) * 8) * 20
                                      + ((q >> 1) * 4)) * 4);
    const uint32_t offB = (uint32_t)(((wn * 16 + lm + (q >> 1) * 8) * 20
                                      + ((q & 1) * 4)) * 4);

    float acc[2][2][4];
#pragma unroll
    for (int mt = 0; mt < 2; mt++)
#pragma unroll
        for (int nt = 0; nt < 2; nt++)
#pragma unroll
            for (int x = 0; x < 4; x++) acc[mt][nt][x] = 0.f;

#define LOAD_CHUNK(ch, st) do {                                              \
        int _kc2 = (ch) * 16;                                                \
        _Pragma("unroll")                                                    \
        for (int _i = 0; _i < 4; _i++) {                                     \
            int _id = tid + _i * 256;                                        \
            int _arr = _id >> 8;                                             \
            int _rem = _id & 255;                                            \
            int _row = _rem >> 2, _seg = _rem & 3;                           \
            const uint32_t* _gp = gsrc[_arr] + (size_t)_row * K2 + _kc2 + _seg * 4; \
            uint32_t _dst = sbase + (st) * STGB + _arr * ARRB                \
                            + (_row * 20 + _seg * 4) * 4;                    \
            CP_ASYNC16(_dst, _gp);                                           \
        }                                                                    \
    } while (0)

#pragma unroll
    for (int s = 0; s < NSTG - 1; s++) {
        LOAD_CHUNK(s, s);
        CP_COMMIT();
    }

    for (int c = 0; c < nch; c++) {
        CP_WAIT(NSTG - 2);
        __syncthreads();
        if (c + NSTG - 1 < nch) {
            int st = (c + NSTG - 1) % NSTG;
            LOAD_CHUNK(c + NSTG - 1, st);
        }
        CP_COMMIT();

        const uint32_t stb = sbase + (c % NSTG) * STGB;
#pragma unroll
        for (int ks = 0; ks < 2; ks++) {
            uint32_t ah0[4], ah1[4], al0[4], al1[4], bh[4], bl[4];
            LDSM_X4(ah0[0], ah0[1], ah0[2], ah0[3], stb + offA + ks * 32);
            LDSM_X4(ah1[0], ah1[1], ah1[2], ah1[3], stb + offA + 1280 + ks * 32);
            LDSM_X4(al0[0], al0[1], al0[2], al0[3], stb + ARRB + offA + ks * 32);
            LDSM_X4(al1[0], al1[1], al1[2], al1[3], stb + ARRB + offA + 1280 + ks * 32);
            LDSM_X4(bh[0],  bh[1],  bh[2],  bh[3],  stb + 2 * ARRB + offB + ks * 32);
            LDSM_X4(bl[0],  bl[1],  bl[2],  bl[3],  stb + 3 * ARRB + offB + ks * 32);
#pragma unroll
            for (int nt = 0; nt < 2; nt++) {
                uint32_t b0 = bh[nt * 2], b1 = bh[nt * 2 + 1];
                uint32_t c0 = bl[nt * 2], c1 = bl[nt * 2 + 1];
                MMA16816(acc[0][nt], ah0[0], ah0[1], ah0[2], ah0[3], b0, b1);
                MMA16816(acc[1][nt], ah1[0], ah1[1], ah1[2], ah1[3], b0, b1);
                MMA16816(acc[0][nt], al0[0], al0[1], al0[2], al0[3], b0, b1);
                MMA16816(acc[1][nt], al1[0], al1[1], al1[2], al1[3], b0, b1);
                MMA16816(acc[0][nt], ah0[0], ah0[1], ah0[2], ah0[3], c0, c1);
                MMA16816(acc[1][nt], ah1[0], ah1[1], ah1[2], ah1[3], c0, c1);
            }
        }
    }
#undef LOAD_CHUNK

    const int col00 = bn * 64 + wn * 16;
    if (mode != 0) {
        float* dst = (mode == 2) ? (bz ? g_hacc2 : g_hacc)
                                 : (bz ? g_wcacc1 : g_wcacc0);
#pragma unroll
        for (int nt = 0; nt < 2; nt++) {
            int col = col00 + nt * 8 + tig * 2;
#pragma unroll
            for (int mt = 0; mt < 2; mt++) {
                int r = bm * 64 + wm * 32 + mt * 16 + gid;
                float* d0 = &dst[(size_t)r * DD + col];
                d0[0] = acc[mt][nt][0];
                d0[1] = acc[mt][nt][1];
                float* d1 = &dst[(size_t)(r + 8) * DD + col];
                d1[0] = acc[mt][nt][2];
                d1[1] = acc[mt][nt][3];
            }
        }
    } else {
#pragma unroll
        for (int nt = 0; nt < 2; nt++) {
            int col = col00 + nt * 8 + tig * 2;
            float bv0 = bias[col], bv1 = bias[col + 1];
#pragma unroll
            for (int mt = 0; mt < 2; mt++) {
                int r = bm * 64 + wm * 32 + mt * 16 + gid;
                float v00 = fmaxf(acc[mt][nt][0] + bv0, 0.f);
                float v01 = fmaxf(acc[mt][nt][1] + bv1, 0.f);
                float v10 = fmaxf(acc[mt][nt][2] + bv0, 0.f);
                float v11 = fmaxf(acc[mt][nt][3] + bv1, 0.f);
                __half2 hp, lp;
                h2split(v00, &hp, &lp, v01);
                *(__half2*)&g_fm1h[(size_t)r * DD + col] = hp;
                *(__half2*)&g_fm1l[(size_t)r * DD + col] = lp;
                h2split(v10, &hp, &lp, v11);
                *(__half2*)&g_fm1h[(size_t)(r + 8) * DD + col] = hp;
                *(__half2*)&g_fm1l[(size_t)(r + 8) * DD + col] = lp;
            }
        }
    }
}

// ---------------- launch: 3-stream graph, split-K GEMMs ----------------------------
extern "C" void kernel_launch(void* const* d_in, const int* in_sizes, int n_in,
                              void* d_out, int out_size) {
    (void)in_sizes; (void)n_in; (void)out_size;
    const float* inputs   = (const float*)d_in[0];
    const int*   bboxes   = (const int*)  d_in[1];
    const float* features = (const float*)d_in[2];
    const float* t1w = (const float*)d_in[3],  *t1b = (const float*)d_in[4];
    const float* t2w = (const float*)d_in[5],  *t2b = (const float*)d_in[6];
    const float* d1w = (const float*)d_in[7],  *d1b = (const float*)d_in[8];
    const float* d2w = (const float*)d_in[9],  *d2b = (const float*)d_in[10];
    const float* m1w = (const float*)d_in[11], *m1b = (const float*)d_in[12];
    const float* m2w = (const float*)d_in[13], *m2b = (const float*)d_in[14];
    const float* pw  = (const float*)d_in[15], *pb  = (const float*)d_in[16];

    float* out      = (float*)d_out;
    float* out_vis  = out;
    float* out_mask = out + VIS_ELEMS;
    float* out_retx = out + VIS_ELEMS + MASK_ELEMS;

    cudaFuncSetAttribute(hgemm, cudaFuncAttributeMaxDynamicSharedMemorySize,
                         GEMM_SMEM);

    static cudaStream_t s2 = nullptr, s3 = nullptr;
    static cudaEvent_t eFork = nullptr, eMean = nullptr, eMeta = nullptr,
                       eB = nullptr, eC = nullptr, eWC = nullptr;
    static float *p_x, *p_h1t, *p_h1d, *p_xt, *p_hb;
    if (s2 == nullptr) {
        cudaStreamCreateWithFlags(&s2, cudaStreamNonBlocking);
        cudaStreamCreateWithFlags(&s3, cudaStreamNonBlocking);
        cudaEventCreateWithFlags(&eFork, cudaEventDisableTiming);
        cudaEventCreateWithFlags(&eMean, cudaEventDisableTiming);
        cudaEventCreateWithFlags(&eMeta, cudaEventDisableTiming);
        cudaEventCreateWithFlags(&eB, cudaEventDisableTiming);
        cudaEventCreateWithFlags(&eC, cudaEventDisableTiming);
        cudaEventCreateWithFlags(&eWC, cudaEventDisableTiming);
        cudaGetSymbolAddress((void**)&p_x,    g_x);
        cudaGetSymbolAddress((void**)&p_h1t,  g_h1t);
        cudaGetSymbolAddress((void**)&p_h1d,  g_h1d);
        cudaGetSymbolAddress((void**)&p_xt,   g_xt);
        cudaGetSymbolAddress((void**)&p_hb,   g_hb);
    }

    // fork
    cudaEventRecord(eFork, 0);
    cudaStreamWaitEvent(s2, eFork, 0);
    cudaStreamWaitEvent(s3, eFork, 0);

    // launch order puts the split-K gemmWC 6th (profiled by ncu -s 5 -c 1)
    mean_partial_kernel<<<BB * NC, 192, 0, s2>>>(inputs);         // 1 (B)
    convp_kernel<<<384, 256, 0, s3>>>(pw);                        // 2 (C)
    w2t_kernel<<<dim3(24, 24), 256, 0, s3>>>(m2w);                // 3 (C)
    mean_final_kernel<<<384, 256, 0, s2>>>();                     // 4 (B)
    cudaEventRecord(eMean, s2);
    cb_kernel<<<96, 256, 0, s3>>>(pw, m2b);                       // 5 (C)
    hgemm<<<dim3(12, 12, 2), 256, GEMM_SMEM, s3>>>(3, nullptr);   // 6 (C) WC <- prof
    wcsplit_kernel<<<576, 256, 0, s3>>>();                        // 7 (C)
    cudaEventRecord(eWC, s3);

    // ---- stream B: t-chain -> hb ----
    mlp2_kernel<<<192, 256, 0, s2>>>(p_x,   t1w, t1b, p_h1t, 1, DD);
    mlp2_kernel<<<192, 256, 0, s2>>>(p_h1t, t2w, t2b, p_xt,  0, DD);
    mlp2_kernel<<<192, 256, 0, s2>>>(p_xt,  pw,  pb,  p_hb,  0, 2 * DD);
    cudaEventRecord(eB, s2);

    // ---- stream C tail: meta, d-chain (ret_x), complement zero ----
    meta_kernel<<<1, NBOX, 0, s3>>>(bboxes, out_mask);
    cudaEventRecord(eMeta, s3);
    cudaStreamWaitEvent(s3, eMean, 0);
    mlp2_kernel<<<192, 256, 0, s3>>>(p_x,   d1w, d1b, p_h1d,   1, DD);
    mlp2_kernel<<<192, 256, 0, s3>>>(p_h1d, d2w, d2b, out_retx, 0, DD);
    zero_comp_kernel<<<512, 256, 0, s3>>>((float4*)out_vis);
    cudaEventRecord(eC, s3);

    // ---- stream A: conv0 -> gemm0 -> (wait WC) -> fused split-K gemm -> epi ----
    conv0_kernel<<<448, 256>>>(m1w, features);
    hgemm<<<dim3(16, 12, 1), 256, GEMM_SMEM>>>(0, m1b);
    cudaStreamWaitEvent(0, eWC, 0);
    hgemm<<<dim3(16, 12, 2), 256, GEMM_SMEM>>>(2, nullptr);

    cudaStreamWaitEvent(0, eB, 0);
    cudaStreamWaitEvent(0, eMeta, 0);
    epi_kernel<<<NBOX, 192>>>(bboxes, out_vis);

    cudaStreamWaitEvent(0, eC, 0);
}